// round 1
// baseline (speedup 1.0000x reference)
#include <cuda_runtime.h>
#include <math.h>

#define Bn 4
#define Cn 128
#define Hn 192
#define Wn 192
#define HW 36864
#define CHW 4718592
#define TOT 18874368
#define NH 2
#define HD 64
#define KSPLIT 144
#define CHUNK 256   // HW / KSPLIT

// ---------------- scratch (static device allocations) ----------------
__device__ float g_B0[TOT];  // xn
__device__ float g_B1[TOT];  // pointwise tmp
__device__ float g_B2[TOT];  // q  -> later o1
__device__ float g_B3[TOT];  // k  -> later o2
__device__ float g_B4[TOT];  // v
__device__ float g_B5[TOT];  // attention out
__device__ float g_nq[512];
__device__ float g_nk[512];
__device__ float g_S[32768];   // (b,n,64,64) raw gram
__device__ float g_A[32768];   // softmax(attn)
__device__ float g_avg[512];
__device__ float g_max[512];
__device__ float g_wtq[16384];
__device__ float g_wtk[16384];
__device__ float g_wtv[16384];
__device__ float g_wt1[16384];
__device__ float g_wt2[16384];
__device__ float g_wtO[32768]; // (ci=256, co=128) transposed

__device__ __forceinline__ float gelu_f(float x){
    return 0.5f * x * (1.0f + erff(x * 0.7071067811865476f));
}

__device__ __forceinline__ void atomicMaxF(float* addr, float v){
    if (v >= 0.0f) atomicMax((int*)addr, __float_as_int(v));
    else           atomicMin((unsigned int*)addr, __float_as_uint(v));
}

// ---------------- weight transpose: (Co,Ci) -> (Ci,Co) ----------------
__global__ void transpose_kernel(const float* __restrict__ src, float* __restrict__ dst,
                                 int Co, int Ci){
    int i = blockIdx.x * 256 + threadIdx.x;
    if (i < Co * Ci){
        int co = i / Ci, ci = i - co * Ci;
        dst[ci * Co + co] = src[i];
    }
}

__global__ void init_kernel(){
    int i = blockIdx.x * 256 + threadIdx.x;
    if (i < 32768) g_S[i] = 0.0f;
    if (i < 512){ g_avg[i] = 0.0f; g_max[i] = __int_as_float(0xff800000); }
}

// ---------------- LayerNorm over channels per pixel ----------------
__global__ void ln_kernel(const float* __restrict__ X, float* __restrict__ Y,
                          const float* __restrict__ w, const float* __restrict__ bias){
    int pix = blockIdx.x * 256 + threadIdx.x;     // exactly B*HW threads
    int b = pix / HW, p = pix - b * HW;
    const float* xb = X + b * CHW + p;
    float s = 0.f, s2 = 0.f;
    #pragma unroll 8
    for (int c = 0; c < Cn; c++){ float v = xb[c * HW]; s += v; s2 += v * v; }
    float mean = s * (1.0f / Cn);
    float var  = s2 * (1.0f / Cn) - mean * mean;
    float rstd = rsqrtf(var + 1e-5f);
    float* yb = Y + b * CHW + p;
    #pragma unroll 8
    for (int c = 0; c < Cn; c++){
        float v = xb[c * HW];
        yb[c * HW] = (v - mean) * rstd * w[c] + bias[c];
    }
}

// ---------------- 1x1 conv, Cin=Cout=128: tile 128co x 64px ----------------
__global__ void pw128_kernel(const float* __restrict__ X, const float* __restrict__ Wt,
                             float* __restrict__ Y, int doGelu){
    __shared__ __align__(16) float sW[8][128];
    __shared__ __align__(16) float sX[8][64];
    int b   = blockIdx.y;
    int px0 = blockIdx.x * 64;
    int tid = threadIdx.x;
    int co0 = (tid >> 4) * 8, pxl = (tid & 15) * 4;
    int wkk = (tid * 4) >> 7, wco = (tid * 4) & 127;
    int xkk = tid >> 5,       xpx = (tid & 31) * 2;
    const float* Xb = X + b * CHW + px0;
    float acc[8][4] = {};
    for (int k0 = 0; k0 < 128; k0 += 8){
        float4 w4 = *(const float4*)(Wt + (k0 + wkk) * 128 + wco);
        float2 x2 = *(const float2*)(Xb + (k0 + xkk) * HW + xpx);
        __syncthreads();
        *(float4*)&sW[wkk][wco] = w4;
        *(float2*)&sX[xkk][xpx] = x2;
        __syncthreads();
        #pragma unroll
        for (int kk = 0; kk < 8; kk++){
            float4 w0 = *(const float4*)&sW[kk][co0];
            float4 w1 = *(const float4*)&sW[kk][co0 + 4];
            float4 xr = *(const float4*)&sX[kk][pxl];
            float wr[8] = {w0.x,w0.y,w0.z,w0.w,w1.x,w1.y,w1.z,w1.w};
            float xv[4] = {xr.x,xr.y,xr.z,xr.w};
            #pragma unroll
            for (int i = 0; i < 8; i++)
                #pragma unroll
                for (int j = 0; j < 4; j++)
                    acc[i][j] = fmaf(wr[i], xv[j], acc[i][j]);
        }
    }
    float* Yb = Y + b * CHW + px0;
    #pragma unroll
    for (int i = 0; i < 8; i++){
        float4 o;
        o.x = acc[i][0]; o.y = acc[i][1]; o.z = acc[i][2]; o.w = acc[i][3];
        if (doGelu){ o.x = gelu_f(o.x); o.y = gelu_f(o.y); o.z = gelu_f(o.z); o.w = gelu_f(o.w); }
        *(float4*)&Yb[(co0 + i) * HW + pxl] = o;
    }
}

// ---------------- depthwise 3x3, pad 1 ----------------
__global__ void dw3_kernel(const float* __restrict__ X, const float* __restrict__ Wd,
                           float* __restrict__ Y){
    int idx = blockIdx.x * 256 + threadIdx.x;     // exactly TOT threads
    int p  = idx % HW;
    int bc = idx / HW;
    int c  = bc & 127;
    int h = p / Wn, w = p - h * Wn;
    const float* xp = X + bc * HW;
    const float* wd = Wd + c * 9;
    float s = 0.f;
    #pragma unroll
    for (int dy = -1; dy <= 1; dy++){
        int hh = h + dy;
        if ((unsigned)hh < Hn){
            #pragma unroll
            for (int dx = -1; dx <= 1; dx++){
                int ww = w + dx;
                if ((unsigned)ww < Wn)
                    s += xp[hh * Wn + ww] * wd[(dy + 1) * 3 + (dx + 1)];
            }
        }
    }
    Y[idx] = s;
}

// ---------------- per-(b,c) L2 norms for q and k ----------------
__global__ void sumsq_kernel(const float* __restrict__ Q, const float* __restrict__ K){
    int plane = blockIdx.x;                        // 0..1023
    const float* src = (plane < 512 ? Q : K) + (plane & 511) * HW;
    float s = 0.f;
    const float4* s4 = (const float4*)src;
    for (int i = threadIdx.x; i < HW / 4; i += 256){
        float4 v = s4[i];
        s += v.x * v.x + v.y * v.y + v.z * v.z + v.w * v.w;
    }
    __shared__ float red[256];
    red[threadIdx.x] = s; __syncthreads();
    for (int st = 128; st > 0; st >>= 1){
        if (threadIdx.x < st) red[threadIdx.x] += red[threadIdx.x + st];
        __syncthreads();
    }
    if (threadIdx.x == 0){
        float n = fmaxf(sqrtf(red[0]), 1e-12f);
        if (plane < 512) g_nq[plane] = n; else g_nk[plane - 512] = n;
    }
}

// ---------------- raw gram S += q k^T, split-K over pixels ----------------
__global__ void gram_kernel(const float* __restrict__ Q, const float* __restrict__ K){
    __shared__ __align__(16) float sq[8][64];
    __shared__ __align__(16) float sk[8][64];
    int bn = blockIdx.y;
    int b = bn >> 1, n = bn & 1;
    const float* Qb = Q + b * CHW + n * HD * HW;
    const float* Kb = K + b * CHW + n * HD * HW;
    int p0 = blockIdx.x * CHUNK;
    int t  = threadIdx.x;                 // 128 threads
    int c0 = (t >> 4) * 8;
    int d0 = (t & 15) * 4;
    int lc = t >> 1;
    int lp = (t & 1) * 4;
    float acc[8][4] = {};
    for (int p = p0; p < p0 + CHUNK; p += 8){
        float4 qa = *(const float4*)(Qb + lc * HW + p + lp);
        float4 ka = *(const float4*)(Kb + lc * HW + p + lp);
        __syncthreads();
        sq[lp+0][lc]=qa.x; sq[lp+1][lc]=qa.y; sq[lp+2][lc]=qa.z; sq[lp+3][lc]=qa.w;
        sk[lp+0][lc]=ka.x; sk[lp+1][lc]=ka.y; sk[lp+2][lc]=ka.z; sk[lp+3][lc]=ka.w;
        __syncthreads();
        #pragma unroll
        for (int pp = 0; pp < 8; pp++){
            float4 w0 = *(const float4*)&sq[pp][c0];
            float4 w1 = *(const float4*)&sq[pp][c0 + 4];
            float4 xr = *(const float4*)&sk[pp][d0];
            float wr[8] = {w0.x,w0.y,w0.z,w0.w,w1.x,w1.y,w1.z,w1.w};
            float xv[4] = {xr.x,xr.y,xr.z,xr.w};
            #pragma unroll
            for (int i = 0; i < 8; i++)
                #pragma unroll
                for (int j = 0; j < 4; j++)
                    acc[i][j] = fmaf(wr[i], xv[j], acc[i][j]);
        }
    }
    float* Sp = g_S + bn * 4096;
    #pragma unroll
    for (int i = 0; i < 8; i++)
        #pragma unroll
        for (int j = 0; j < 4; j++)
            atomicAdd(&Sp[(c0 + i) * 64 + d0 + j], acc[i][j]);
}

// ---------------- finalize attn (write attn_weight) + softmax ----------------
__global__ void attnfin_kernel(const float* __restrict__ scale, float* __restrict__ outAttn){
    int row = blockIdx.x;        // b*128 + n*64 + c
    int d   = threadIdx.x;       // 64
    int b = row >> 7;
    int r = row & 127;
    int n = r >> 6;
    float val = g_S[row * 64 + d] / (g_nq[b * 128 + r] * g_nk[b * 128 + (n << 6) + d]) * scale[n];
    outAttn[row * 64 + d] = val;
    __shared__ float sm[64];
    sm[d] = val; __syncthreads();
    for (int st = 32; st > 0; st >>= 1){ if (d < st) sm[d] = fmaxf(sm[d], sm[d + st]); __syncthreads(); }
    float mx = sm[0]; __syncthreads();
    float e = expf(val - mx);
    sm[d] = e; __syncthreads();
    for (int st = 32; st > 0; st >>= 1){ if (d < st) sm[d] += sm[d + st]; __syncthreads(); }
    g_A[row * 64 + d] = e / sm[0];
}

// ---------------- out = a @ v : tile 64c x 64px, K=64 ----------------
__global__ void applyav_kernel(const float* __restrict__ V, float* __restrict__ Out){
    __shared__ __align__(16) float sA[8][64];
    __shared__ __align__(16) float sV[8][64];
    int bn = blockIdx.y;
    int b = bn >> 1, n = bn & 1;
    const float* Vb = V + b * CHW + n * HD * HW;
    const float* Ab = g_A + bn * 4096;
    int px0 = blockIdx.x * 64;
    int t = threadIdx.x;                 // 128
    int c0 = (t >> 4) * 8, pl = (t & 15) * 4;
    int lc = t >> 1,      ld = (t & 1) * 4;
    int vk = t >> 4,      vp = (t & 15) * 4;
    float acc[8][4] = {};
    for (int dd = 0; dd < 64; dd += 8){
        float4 a4 = *(const float4*)(Ab + lc * 64 + dd + ld);
        float4 v4 = *(const float4*)(Vb + (dd + vk) * HW + px0 + vp);
        __syncthreads();
        sA[ld+0][lc]=a4.x; sA[ld+1][lc]=a4.y; sA[ld+2][lc]=a4.z; sA[ld+3][lc]=a4.w;
        *(float4*)&sV[vk][vp] = v4;
        __syncthreads();
        #pragma unroll
        for (int pp = 0; pp < 8; pp++){
            float4 a0 = *(const float4*)&sA[pp][c0];
            float4 a1 = *(const float4*)&sA[pp][c0 + 4];
            float4 vr = *(const float4*)&sV[pp][pl];
            float ar[8] = {a0.x,a0.y,a0.z,a0.w,a1.x,a1.y,a1.z,a1.w};
            float vv[4] = {vr.x,vr.y,vr.z,vr.w};
            #pragma unroll
            for (int i = 0; i < 8; i++)
                #pragma unroll
                for (int j = 0; j < 4; j++)
                    acc[i][j] = fmaf(ar[i], vv[j], acc[i][j]);
        }
    }
    float* Ob = Out + b * CHW + n * HD * HW + px0;
    #pragma unroll
    for (int i = 0; i < 8; i++){
        float4 o; o.x = acc[i][0]; o.y = acc[i][1]; o.z = acc[i][2]; o.w = acc[i][3];
        *(float4*)&Ob[(c0 + i) * HW + pl] = o;
    }
}

// ---------------- fused f_out conv (256->128) + gelu input + avg/max pool ----------------
__global__ void foutpool_kernel(const float* __restrict__ O1, const float* __restrict__ O2){
    __shared__ __align__(16) float sW[8][128];
    __shared__ __align__(16) float sX[8][64];
    __shared__ float ssum[128];
    __shared__ float smax[128];
    int b   = blockIdx.y;
    int px0 = blockIdx.x * 64;
    int tid = threadIdx.x;
    if (tid < 128){ ssum[tid] = 0.f; smax[tid] = __int_as_float(0xff800000); }
    int co0 = (tid >> 4) * 8, pxl = (tid & 15) * 4;
    int wkk = (tid * 4) >> 7, wco = (tid * 4) & 127;
    int xkk = tid >> 5,       xpx = (tid & 31) * 2;
    float acc[8][4] = {};
    for (int k0 = 0; k0 < 256; k0 += 8){
        float4 w4 = *(const float4*)(g_wtO + (k0 + wkk) * 128 + wco);
        int ci = k0 + xkk;
        const float* src = (ci < 128) ? (O1 + b * CHW + ci * HW)
                                      : (O2 + b * CHW + (ci - 128) * HW);
        float2 x2 = *(const float2*)(src + px0 + xpx);
        x2.x = gelu_f(x2.x); x2.y = gelu_f(x2.y);
        __syncthreads();
        *(float4*)&sW[wkk][wco] = w4;
        *(float2*)&sX[xkk][xpx] = x2;
        __syncthreads();
        #pragma unroll
        for (int kk = 0; kk < 8; kk++){
            float4 w0 = *(const float4*)&sW[kk][co0];
            float4 w1 = *(const float4*)&sW[kk][co0 + 4];
            float4 xr = *(const float4*)&sX[kk][pxl];
            float wr[8] = {w0.x,w0.y,w0.z,w0.w,w1.x,w1.y,w1.z,w1.w};
            float xv[4] = {xr.x,xr.y,xr.z,xr.w};
            #pragma unroll
            for (int i = 0; i < 8; i++)
                #pragma unroll
                for (int j = 0; j < 4; j++)
                    acc[i][j] = fmaf(wr[i], xv[j], acc[i][j]);
        }
    }
    #pragma unroll
    for (int i = 0; i < 8; i++){
        float s = acc[i][0] + acc[i][1] + acc[i][2] + acc[i][3];
        float m = fmaxf(fmaxf(acc[i][0], acc[i][1]), fmaxf(acc[i][2], acc[i][3]));
        atomicAdd(&ssum[co0 + i], s);
        atomicMaxF(&smax[co0 + i], m);
    }
    __syncthreads();
    if (tid < 128){
        atomicAdd(&g_avg[b * 128 + tid], ssum[tid]);
        atomicMaxF(&g_max[b * 128 + tid], smax[tid]);
    }
}

// ---------------- channel gate MLP -> sigmoid -> spec_score ----------------
__global__ void gate_kernel(const float* __restrict__ w1, const float* __restrict__ b1,
                            const float* __restrict__ w2, const float* __restrict__ b2,
                            float* __restrict__ out){
    int b = blockIdx.x;
    int c = threadIdx.x;   // 128
    __shared__ float avg[128], mx[128], ha[8], hm[8];
    avg[c] = g_avg[b * 128 + c] * (1.0f / HW);
    mx[c]  = g_max[b * 128 + c];
    __syncthreads();
    if (c < 8){
        float sa = b1[c], sm_ = b1[c];
        for (int j = 0; j < 128; j++){
            sa  += w1[c * 128 + j] * avg[j];
            sm_ += w1[c * 128 + j] * mx[j];
        }
        ha[c] = fmaxf(sa, 0.f);
        hm[c] = fmaxf(sm_, 0.f);
    }
    __syncthreads();
    float z = 2.0f * b2[c];
    for (int j = 0; j < 8; j++) z += (ha[j] + hm[j]) * w2[c * 8 + j];
    out[b * 128 + c] = 1.0f / (1.0f + expf(-z));
}

// ---------------- launch ----------------
extern "C" void kernel_launch(void* const* d_in, const int* in_sizes, int n_in,
                              void* d_out, int out_size){
    const float* x        = (const float*)d_in[0];
    const float* ln_in_w  = (const float*)d_in[1];
    const float* ln_in_b  = (const float*)d_in[2];
    const float* wq_pw    = (const float*)d_in[3];
    const float* wq_dw    = (const float*)d_in[4];
    const float* wk_pw    = (const float*)d_in[5];
    const float* wk_dw    = (const float*)d_in[6];
    const float* wv_pw    = (const float*)d_in[7];
    const float* wv_dw    = (const float*)d_in[8];
    const float* scale    = (const float*)d_in[9];
    const float* ln_out_w = (const float*)d_in[10];
    const float* ln_out_b = (const float*)d_in[11];
    const float* f1_pw    = (const float*)d_in[12];
    const float* f1_dw    = (const float*)d_in[13];
    const float* f2_pw    = (const float*)d_in[14];
    const float* f2_dw    = (const float*)d_in[15];
    const float* f_out    = (const float*)d_in[16];
    const float* gw1      = (const float*)d_in[17];
    const float* gb1      = (const float*)d_in[18];
    const float* gw2      = (const float*)d_in[19];
    const float* gb2      = (const float*)d_in[20];
    float* out = (float*)d_out;

    void *p;
    float *B0,*B1,*B2,*B3,*B4,*B5,*WTQ,*WTK,*WTV,*WT1,*WT2,*WTO;
    cudaGetSymbolAddress(&p, g_B0);  B0  = (float*)p;
    cudaGetSymbolAddress(&p, g_B1);  B1  = (float*)p;
    cudaGetSymbolAddress(&p, g_B2);  B2  = (float*)p;
    cudaGetSymbolAddress(&p, g_B3);  B3  = (float*)p;
    cudaGetSymbolAddress(&p, g_B4);  B4  = (float*)p;
    cudaGetSymbolAddress(&p, g_B5);  B5  = (float*)p;
    cudaGetSymbolAddress(&p, g_wtq); WTQ = (float*)p;
    cudaGetSymbolAddress(&p, g_wtk); WTK = (float*)p;
    cudaGetSymbolAddress(&p, g_wtv); WTV = (float*)p;
    cudaGetSymbolAddress(&p, g_wt1); WT1 = (float*)p;
    cudaGetSymbolAddress(&p, g_wt2); WT2 = (float*)p;
    cudaGetSymbolAddress(&p, g_wtO); WTO = (float*)p;

    dim3 gpx(576, Bn);

    transpose_kernel<<<64, 256>>>(wq_pw, WTQ, 128, 128);
    transpose_kernel<<<64, 256>>>(wk_pw, WTK, 128, 128);
    transpose_kernel<<<64, 256>>>(wv_pw, WTV, 128, 128);
    transpose_kernel<<<64, 256>>>(f1_pw, WT1, 128, 128);
    transpose_kernel<<<64, 256>>>(f2_pw, WT2, 128, 128);
    transpose_kernel<<<128, 256>>>(f_out, WTO, 128, 256);
    init_kernel<<<128, 256>>>();

    ln_kernel<<<576, 256>>>(x, B0, ln_in_w, ln_in_b);

    pw128_kernel<<<gpx, 256>>>(B0, WTQ, B1, 0);
    dw3_kernel<<<73728, 256>>>(B1, wq_dw, B2);
    pw128_kernel<<<gpx, 256>>>(B0, WTK, B1, 0);
    dw3_kernel<<<73728, 256>>>(B1, wk_dw, B3);
    pw128_kernel<<<gpx, 256>>>(B0, WTV, B1, 0);
    dw3_kernel<<<73728, 256>>>(B1, wv_dw, B4);

    sumsq_kernel<<<1024, 256>>>(B2, B3);
    gram_kernel<<<dim3(KSPLIT, 8), 128>>>(B2, B3);
    attnfin_kernel<<<512, 64>>>(scale, out + 512);
    applyav_kernel<<<dim3(576, 8), 128>>>(B4, B5);

    ln_kernel<<<576, 256>>>(B5, B5, ln_out_w, ln_out_b);

    pw128_kernel<<<gpx, 256>>>(B5, WT1, B1, 1);
    dw3_kernel<<<73728, 256>>>(B1, f1_dw, B2);
    pw128_kernel<<<gpx, 256>>>(B5, WT2, B1, 1);
    dw3_kernel<<<73728, 256>>>(B1, f2_dw, B3);

    foutpool_kernel<<<gpx, 256>>>(B2, B3);
    gate_kernel<<<4, 128>>>(gw1, gb1, gw2, gb2, out);
}

// round 2
// speedup vs baseline: 1.1700x; 1.1700x over previous
#include <cuda_runtime.h>
#include <math.h>

#define Bn 4
#define Cn 128
#define Hn 192
#define Wn 192
#define HW 36864
#define CHW 4718592
#define TOT 18874368
#define NH 2
#define HD 64
#define KSPLIT 144
#define CHUNK 256   // HW / KSPLIT

typedef unsigned long long u64t;

// ---------------- scratch (static device allocations) ----------------
__device__ float g_B0[TOT];  // xn
__device__ float g_B1[TOT];  // pointwise tmp
__device__ float g_B2[TOT];  // q  -> later o1
__device__ float g_B3[TOT];  // k  -> later o2
__device__ float g_B4[TOT];  // v
__device__ float g_B5[TOT];  // attention out
__device__ float g_sq[1024];   // sumsq for q (0..511) and k (512..1023)
__device__ float g_S[32768];   // (b,n,64,64) raw gram
__device__ float g_A[32768];   // softmax(attn)
__device__ float g_avg[512];
__device__ float g_max[512];
__device__ float g_wtq[16384];
__device__ float g_wtk[16384];
__device__ float g_wtv[16384];
__device__ float g_wt1[16384];
__device__ float g_wt2[16384];
__device__ float g_wtO[32768]; // (ci=256, co=128) transposed

__device__ __forceinline__ float gelu_f(float x){
    return 0.5f * x * (1.0f + erff(x * 0.7071067811865476f));
}

__device__ __forceinline__ void atomicMaxF(float* addr, float v){
    if (v >= 0.0f) atomicMax((int*)addr, __float_as_int(v));
    else           atomicMin((unsigned int*)addr, __float_as_uint(v));
}

// packed fp32x2 helpers (Blackwell FFMA2 path)
__device__ __forceinline__ u64t pack2(float lo, float hi){
    u64t r; asm("mov.b64 %0, {%1, %2};" : "=l"(r) : "f"(lo), "f"(hi)); return r;
}
__device__ __forceinline__ void ffma2(u64t& d, u64t a, u64t b){
    asm("fma.rn.f32x2 %0, %1, %2, %0;" : "+l"(d) : "l"(a), "l"(b));
}
__device__ __forceinline__ float2 unpack2(u64t v){
    float2 f; asm("mov.b64 {%0, %1}, %2;" : "=f"(f.x), "=f"(f.y) : "l"(v)); return f;
}

// ---------------- weight transpose: (Co,Ci) -> (Ci,Co) ----------------
__global__ void transpose_kernel(const float* __restrict__ src, float* __restrict__ dst,
                                 int Co, int Ci){
    int i = blockIdx.x * 256 + threadIdx.x;
    if (i < Co * Ci){
        int co = i / Ci, ci = i - co * Ci;
        dst[ci * Co + co] = src[i];
    }
}

__global__ void init_kernel(){
    int i = blockIdx.x * 256 + threadIdx.x;
    if (i < 32768) g_S[i] = 0.0f;
    if (i < 1024) g_sq[i] = 0.0f;
    if (i < 512){ g_avg[i] = 0.0f; g_max[i] = __int_as_float(0xff800000); }
}

// ---------------- LayerNorm over channels per pixel ----------------
__global__ void ln_kernel(const float* __restrict__ X, float* __restrict__ Y,
                          const float* __restrict__ w, const float* __restrict__ bias){
    int pix = blockIdx.x * 256 + threadIdx.x;     // exactly B*HW threads
    int b = pix / HW, p = pix - b * HW;
    const float* xb = X + b * CHW + p;
    float s = 0.f, s2 = 0.f;
    #pragma unroll 8
    for (int c = 0; c < Cn; c++){ float v = xb[c * HW]; s += v; s2 += v * v; }
    float mean = s * (1.0f / Cn);
    float var  = s2 * (1.0f / Cn) - mean * mean;
    float rstd = rsqrtf(var + 1e-5f);
    float* yb = Y + b * CHW + p;
    #pragma unroll 8
    for (int c = 0; c < Cn; c++){
        float v = xb[c * HW];
        yb[c * HW] = (v - mean) * rstd * w[c] + bias[c];
    }
}

// ---------------- 1x1 conv 128->128, f32x2: tile 128co x 128px ----------------
__global__ void pw128_kernel(const float* __restrict__ X, const float* __restrict__ Wt,
                             float* __restrict__ Y, int doGelu){
    __shared__ __align__(16) float sW[8][128];
    __shared__ __align__(16) float sX[8][128];
    int b   = blockIdx.y;
    int px0 = blockIdx.x * 128;
    int tid = threadIdx.x;
    int co0 = (tid >> 4) * 8, pxl = (tid & 15) * 8;
    int ldr = tid >> 5, ldc = (tid & 31) * 4;
    const float* Xb = X + b * CHW + px0;
    u64t acc[8][4];
    #pragma unroll
    for (int i = 0; i < 8; i++)
        #pragma unroll
        for (int j = 0; j < 4; j++) acc[i][j] = 0ull;

    for (int k0 = 0; k0 < 128; k0 += 8){
        float4 w4 = *(const float4*)(Wt + (k0 + ldr) * 128 + ldc);
        float4 x4 = *(const float4*)(Xb + (k0 + ldr) * HW + ldc);
        __syncthreads();
        *(float4*)&sW[ldr][ldc] = w4;
        *(float4*)&sX[ldr][ldc] = x4;
        __syncthreads();
        #pragma unroll
        for (int kk = 0; kk < 8; kk++){
            float4 wa = *(const float4*)&sW[kk][co0];
            float4 wb = *(const float4*)&sW[kk][co0 + 4];
            float4 xa = *(const float4*)&sX[kk][pxl];
            float4 xb = *(const float4*)&sX[kk][pxl + 4];
            u64t xp[4] = {pack2(xa.x, xa.y), pack2(xa.z, xa.w),
                          pack2(xb.x, xb.y), pack2(xb.z, xb.w)};
            float wr[8] = {wa.x,wa.y,wa.z,wa.w,wb.x,wb.y,wb.z,wb.w};
            #pragma unroll
            for (int i = 0; i < 8; i++){
                u64t wd = pack2(wr[i], wr[i]);
                #pragma unroll
                for (int j = 0; j < 4; j++) ffma2(acc[i][j], wd, xp[j]);
            }
        }
    }
    float* Yb = Y + b * CHW + px0;
    #pragma unroll
    for (int i = 0; i < 8; i++){
        float2 r0 = unpack2(acc[i][0]), r1 = unpack2(acc[i][1]);
        float2 r2 = unpack2(acc[i][2]), r3 = unpack2(acc[i][3]);
        float4 o0, o1;
        o0.x=r0.x; o0.y=r0.y; o0.z=r1.x; o0.w=r1.y;
        o1.x=r2.x; o1.y=r2.y; o1.z=r3.x; o1.w=r3.y;
        if (doGelu){
            o0.x=gelu_f(o0.x); o0.y=gelu_f(o0.y); o0.z=gelu_f(o0.z); o0.w=gelu_f(o0.w);
            o1.x=gelu_f(o1.x); o1.y=gelu_f(o1.y); o1.z=gelu_f(o1.z); o1.w=gelu_f(o1.w);
        }
        *(float4*)&Yb[(co0 + i) * HW + pxl]     = o0;
        *(float4*)&Yb[(co0 + i) * HW + pxl + 4] = o1;
    }
}

// ---------------- depthwise 3x3 pad 1, 4px/thread, optional fused sumsq ----------------
__global__ void dw3_kernel(const float* __restrict__ X, const float* __restrict__ Wd,
                           float* __restrict__ Y, float* __restrict__ sq){
    int idx = blockIdx.x * 256 + threadIdx.x;     // TOT/4 threads
    int plane = idx / (HW / 4);                   // b*128 + c
    int pin   = (idx - plane * (HW / 4)) * 4;
    int c = plane & 127;
    int h = pin / Wn, w = pin - h * Wn;           // w is multiple of 4
    const float* xp = X + plane * HW;
    const float* wd = Wd + c * 9;
    float o0 = 0.f, o1 = 0.f, o2 = 0.f, o3 = 0.f;
    #pragma unroll
    for (int dy = -1; dy <= 1; dy++){
        int hh = h + dy;
        if ((unsigned)hh >= Hn) continue;
        const float* r = xp + hh * Wn + w;
        float4 c4 = *(const float4*)r;
        float lm = (w > 0)        ? r[-1] : 0.f;
        float rp = (w + 4 < Wn)   ? r[4]  : 0.f;
        float k0 = wd[(dy + 1) * 3 + 0], k1 = wd[(dy + 1) * 3 + 1], k2 = wd[(dy + 1) * 3 + 2];
        o0 = fmaf(lm,   k0, fmaf(c4.x, k1, fmaf(c4.y, k2, o0)));
        o1 = fmaf(c4.x, k0, fmaf(c4.y, k1, fmaf(c4.z, k2, o1)));
        o2 = fmaf(c4.y, k0, fmaf(c4.z, k1, fmaf(c4.w, k2, o2)));
        o3 = fmaf(c4.z, k0, fmaf(c4.w, k1, fmaf(rp,   k2, o3)));
    }
    float4 o; o.x = o0; o.y = o1; o.z = o2; o.w = o3;
    *(float4*)&Y[plane * HW + pin] = o;
    if (sq){
        // all 32 lanes of a warp are in the same plane (HW/4 = 9216, divisible by 32)
        float s = o0*o0 + o1*o1 + o2*o2 + o3*o3;
        #pragma unroll
        for (int st = 16; st > 0; st >>= 1)
            s += __shfl_down_sync(0xffffffffu, s, st);
        if ((threadIdx.x & 31) == 0) atomicAdd(&sq[plane], s);
    }
}

// ---------------- raw gram S += q k^T, split-K over pixels ----------------
__global__ void gram_kernel(const float* __restrict__ Q, const float* __restrict__ K){
    __shared__ __align__(16) float sq[8][64];
    __shared__ __align__(16) float sk[8][64];
    int bn = blockIdx.y;
    int b = bn >> 1, n = bn & 1;
    const float* Qb = Q + b * CHW + n * HD * HW;
    const float* Kb = K + b * CHW + n * HD * HW;
    int p0 = blockIdx.x * CHUNK;
    int t  = threadIdx.x;                 // 128 threads
    int c0 = (t >> 4) * 8;
    int d0 = (t & 15) * 4;
    int lc = t >> 1;
    int lp = (t & 1) * 4;
    float acc[8][4] = {};
    for (int p = p0; p < p0 + CHUNK; p += 8){
        float4 qa = *(const float4*)(Qb + lc * HW + p + lp);
        float4 ka = *(const float4*)(Kb + lc * HW + p + lp);
        __syncthreads();
        sq[lp+0][lc]=qa.x; sq[lp+1][lc]=qa.y; sq[lp+2][lc]=qa.z; sq[lp+3][lc]=qa.w;
        sk[lp+0][lc]=ka.x; sk[lp+1][lc]=ka.y; sk[lp+2][lc]=ka.z; sk[lp+3][lc]=ka.w;
        __syncthreads();
        #pragma unroll
        for (int pp = 0; pp < 8; pp++){
            float4 w0 = *(const float4*)&sq[pp][c0];
            float4 w1 = *(const float4*)&sq[pp][c0 + 4];
            float4 xr = *(const float4*)&sk[pp][d0];
            float wr[8] = {w0.x,w0.y,w0.z,w0.w,w1.x,w1.y,w1.z,w1.w};
            float xv[4] = {xr.x,xr.y,xr.z,xr.w};
            #pragma unroll
            for (int i = 0; i < 8; i++)
                #pragma unroll
                for (int j = 0; j < 4; j++)
                    acc[i][j] = fmaf(wr[i], xv[j], acc[i][j]);
        }
    }
    float* Sp = g_S + bn * 4096;
    #pragma unroll
    for (int i = 0; i < 8; i++)
        #pragma unroll
        for (int j = 0; j < 4; j++)
            atomicAdd(&Sp[(c0 + i) * 64 + d0 + j], acc[i][j]);
}

// ---------------- finalize attn (write attn_weight) + softmax ----------------
__global__ void attnfin_kernel(const float* __restrict__ scale, float* __restrict__ outAttn){
    int row = blockIdx.x;        // b*128 + n*64 + c
    int d   = threadIdx.x;       // 64
    int b = row >> 7;
    int r = row & 127;
    int n = r >> 6;
    float nq = fmaxf(sqrtf(g_sq[b * 128 + r]), 1e-12f);
    float nk = fmaxf(sqrtf(g_sq[512 + b * 128 + (n << 6) + d]), 1e-12f);
    float val = g_S[row * 64 + d] / (nq * nk) * scale[n];
    outAttn[row * 64 + d] = val;
    __shared__ float sm[64];
    sm[d] = val; __syncthreads();
    for (int st = 32; st > 0; st >>= 1){ if (d < st) sm[d] = fmaxf(sm[d], sm[d + st]); __syncthreads(); }
    float mx = sm[0]; __syncthreads();
    float e = expf(val - mx);
    sm[d] = e; __syncthreads();
    for (int st = 32; st > 0; st >>= 1){ if (d < st) sm[d] += sm[d + st]; __syncthreads(); }
    g_A[row * 64 + d] = e / sm[0];
}

// ---------------- out = a @ v : tile 64c x 64px, K=64 ----------------
__global__ void applyav_kernel(const float* __restrict__ V, float* __restrict__ Out){
    __shared__ __align__(16) float sA[8][64];
    __shared__ __align__(16) float sV[8][64];
    int bn = blockIdx.y;
    int b = bn >> 1, n = bn & 1;
    const float* Vb = V + b * CHW + n * HD * HW;
    const float* Ab = g_A + bn * 4096;
    int px0 = blockIdx.x * 64;
    int t = threadIdx.x;                 // 128
    int c0 = (t >> 4) * 8, pl = (t & 15) * 4;
    int lc = t >> 1,      ld = (t & 1) * 4;
    int vk = t >> 4,      vp = (t & 15) * 4;
    float acc[8][4] = {};
    for (int dd = 0; dd < 64; dd += 8){
        float4 a4 = *(const float4*)(Ab + lc * 64 + dd + ld);
        float4 v4 = *(const float4*)(Vb + (dd + vk) * HW + px0 + vp);
        __syncthreads();
        sA[ld+0][lc]=a4.x; sA[ld+1][lc]=a4.y; sA[ld+2][lc]=a4.z; sA[ld+3][lc]=a4.w;
        *(float4*)&sV[vk][vp] = v4;
        __syncthreads();
        #pragma unroll
        for (int pp = 0; pp < 8; pp++){
            float4 a0 = *(const float4*)&sA[pp][c0];
            float4 a1 = *(const float4*)&sA[pp][c0 + 4];
            float4 vr = *(const float4*)&sV[pp][pl];
            float ar[8] = {a0.x,a0.y,a0.z,a0.w,a1.x,a1.y,a1.z,a1.w};
            float vv[4] = {vr.x,vr.y,vr.z,vr.w};
            #pragma unroll
            for (int i = 0; i < 8; i++)
                #pragma unroll
                for (int j = 0; j < 4; j++)
                    acc[i][j] = fmaf(ar[i], vv[j], acc[i][j]);
        }
    }
    float* Ob = Out + b * CHW + n * HD * HW + px0;
    #pragma unroll
    for (int i = 0; i < 8; i++){
        float4 o; o.x = acc[i][0]; o.y = acc[i][1]; o.z = acc[i][2]; o.w = acc[i][3];
        *(float4*)&Ob[(c0 + i) * HW + pl] = o;
    }
}

// ---------- fused f_out conv (256->128, f32x2) + gelu input + avg/max pool ----------
__global__ void foutpool_kernel(const float* __restrict__ O1, const float* __restrict__ O2){
    __shared__ __align__(16) float sW[8][128];
    __shared__ __align__(16) float sX[8][128];
    __shared__ float ssum[128];
    __shared__ float smax[128];
    int b   = blockIdx.y;
    int px0 = blockIdx.x * 128;
    int tid = threadIdx.x;
    if (tid < 128){ ssum[tid] = 0.f; smax[tid] = __int_as_float(0xff800000); }
    int co0 = (tid >> 4) * 8, pxl = (tid & 15) * 8;
    int ldr = tid >> 5, ldc = (tid & 31) * 4;
    u64t acc[8][4];
    #pragma unroll
    for (int i = 0; i < 8; i++)
        #pragma unroll
        for (int j = 0; j < 4; j++) acc[i][j] = 0ull;

    for (int k0 = 0; k0 < 256; k0 += 8){
        float4 w4 = *(const float4*)(g_wtO + (k0 + ldr) * 128 + ldc);
        int ci = k0 + ldr;
        const float* src = (ci < 128) ? (O1 + b * CHW + ci * HW)
                                      : (O2 + b * CHW + (ci - 128) * HW);
        float4 x4 = *(const float4*)(src + px0 + ldc);
        x4.x = gelu_f(x4.x); x4.y = gelu_f(x4.y); x4.z = gelu_f(x4.z); x4.w = gelu_f(x4.w);
        __syncthreads();
        *(float4*)&sW[ldr][ldc] = w4;
        *(float4*)&sX[ldr][ldc] = x4;
        __syncthreads();
        #pragma unroll
        for (int kk = 0; kk < 8; kk++){
            float4 wa = *(const float4*)&sW[kk][co0];
            float4 wb = *(const float4*)&sW[kk][co0 + 4];
            float4 xa = *(const float4*)&sX[kk][pxl];
            float4 xb = *(const float4*)&sX[kk][pxl + 4];
            u64t xp[4] = {pack2(xa.x, xa.y), pack2(xa.z, xa.w),
                          pack2(xb.x, xb.y), pack2(xb.z, xb.w)};
            float wr[8] = {wa.x,wa.y,wa.z,wa.w,wb.x,wb.y,wb.z,wb.w};
            #pragma unroll
            for (int i = 0; i < 8; i++){
                u64t wd = pack2(wr[i], wr[i]);
                #pragma unroll
                for (int j = 0; j < 4; j++) ffma2(acc[i][j], wd, xp[j]);
            }
        }
    }
    #pragma unroll
    for (int i = 0; i < 8; i++){
        float2 r0 = unpack2(acc[i][0]), r1 = unpack2(acc[i][1]);
        float2 r2 = unpack2(acc[i][2]), r3 = unpack2(acc[i][3]);
        float s = (r0.x + r0.y) + (r1.x + r1.y) + (r2.x + r2.y) + (r3.x + r3.y);
        float m = fmaxf(fmaxf(fmaxf(r0.x, r0.y), fmaxf(r1.x, r1.y)),
                        fmaxf(fmaxf(r2.x, r2.y), fmaxf(r3.x, r3.y)));
        atomicAdd(&ssum[co0 + i], s);
        atomicMaxF(&smax[co0 + i], m);
    }
    __syncthreads();
    if (tid < 128){
        atomicAdd(&g_avg[b * 128 + tid], ssum[tid]);
        atomicMaxF(&g_max[b * 128 + tid], smax[tid]);
    }
}

// ---------------- channel gate MLP -> sigmoid -> spec_score ----------------
__global__ void gate_kernel(const float* __restrict__ w1, const float* __restrict__ b1,
                            const float* __restrict__ w2, const float* __restrict__ b2,
                            float* __restrict__ out){
    int b = blockIdx.x;
    int c = threadIdx.x;   // 128
    __shared__ float avg[128], mx[128], ha[8], hm[8];
    avg[c] = g_avg[b * 128 + c] * (1.0f / HW);
    mx[c]  = g_max[b * 128 + c];
    __syncthreads();
    if (c < 8){
        float sa = b1[c], sm_ = b1[c];
        for (int j = 0; j < 128; j++){
            sa  += w1[c * 128 + j] * avg[j];
            sm_ += w1[c * 128 + j] * mx[j];
        }
        ha[c] = fmaxf(sa, 0.f);
        hm[c] = fmaxf(sm_, 0.f);
    }
    __syncthreads();
    float z = 2.0f * b2[c];
    for (int j = 0; j < 8; j++) z += (ha[j] + hm[j]) * w2[c * 8 + j];
    out[b * 128 + c] = 1.0f / (1.0f + expf(-z));
}

// ---------------- launch ----------------
extern "C" void kernel_launch(void* const* d_in, const int* in_sizes, int n_in,
                              void* d_out, int out_size){
    const float* x        = (const float*)d_in[0];
    const float* ln_in_w  = (const float*)d_in[1];
    const float* ln_in_b  = (const float*)d_in[2];
    const float* wq_pw    = (const float*)d_in[3];
    const float* wq_dw    = (const float*)d_in[4];
    const float* wk_pw    = (const float*)d_in[5];
    const float* wk_dw    = (const float*)d_in[6];
    const float* wv_pw    = (const float*)d_in[7];
    const float* wv_dw    = (const float*)d_in[8];
    const float* scale    = (const float*)d_in[9];
    const float* ln_out_w = (const float*)d_in[10];
    const float* ln_out_b = (const float*)d_in[11];
    const float* f1_pw    = (const float*)d_in[12];
    const float* f1_dw    = (const float*)d_in[13];
    const float* f2_pw    = (const float*)d_in[14];
    const float* f2_dw    = (const float*)d_in[15];
    const float* f_out    = (const float*)d_in[16];
    const float* gw1      = (const float*)d_in[17];
    const float* gb1      = (const float*)d_in[18];
    const float* gw2      = (const float*)d_in[19];
    const float* gb2      = (const float*)d_in[20];
    float* out = (float*)d_out;

    void *p;
    float *B0,*B1,*B2,*B3,*B4,*B5,*SQ,*WTQ,*WTK,*WTV,*WT1,*WT2,*WTO;
    cudaGetSymbolAddress(&p, g_B0);  B0  = (float*)p;
    cudaGetSymbolAddress(&p, g_B1);  B1  = (float*)p;
    cudaGetSymbolAddress(&p, g_B2);  B2  = (float*)p;
    cudaGetSymbolAddress(&p, g_B3);  B3  = (float*)p;
    cudaGetSymbolAddress(&p, g_B4);  B4  = (float*)p;
    cudaGetSymbolAddress(&p, g_B5);  B5  = (float*)p;
    cudaGetSymbolAddress(&p, g_sq);  SQ  = (float*)p;
    cudaGetSymbolAddress(&p, g_wtq); WTQ = (float*)p;
    cudaGetSymbolAddress(&p, g_wtk); WTK = (float*)p;
    cudaGetSymbolAddress(&p, g_wtv); WTV = (float*)p;
    cudaGetSymbolAddress(&p, g_wt1); WT1 = (float*)p;
    cudaGetSymbolAddress(&p, g_wt2); WT2 = (float*)p;
    cudaGetSymbolAddress(&p, g_wtO); WTO = (float*)p;

    dim3 gpx(288, Bn);
    const int dwBlocks = TOT / 4 / 256;

    transpose_kernel<<<64, 256>>>(wq_pw, WTQ, 128, 128);
    transpose_kernel<<<64, 256>>>(wk_pw, WTK, 128, 128);
    transpose_kernel<<<64, 256>>>(wv_pw, WTV, 128, 128);
    transpose_kernel<<<64, 256>>>(f1_pw, WT1, 128, 128);
    transpose_kernel<<<64, 256>>>(f2_pw, WT2, 128, 128);
    transpose_kernel<<<128, 256>>>(f_out, WTO, 128, 256);
    init_kernel<<<128, 256>>>();

    ln_kernel<<<576, 256>>>(x, B0, ln_in_w, ln_in_b);

    pw128_kernel<<<gpx, 256>>>(B0, WTQ, B1, 0);
    dw3_kernel<<<dwBlocks, 256>>>(B1, wq_dw, B2, SQ);
    pw128_kernel<<<gpx, 256>>>(B0, WTK, B1, 0);
    dw3_kernel<<<dwBlocks, 256>>>(B1, wk_dw, B3, SQ + 512);
    pw128_kernel<<<gpx, 256>>>(B0, WTV, B1, 0);
    dw3_kernel<<<dwBlocks, 256>>>(B1, wv_dw, B4, nullptr);

    gram_kernel<<<dim3(KSPLIT, 8), 128>>>(B2, B3);
    attnfin_kernel<<<512, 64>>>(scale, out + 512);
    applyav_kernel<<<dim3(576, 8), 128>>>(B4, B5);

    ln_kernel<<<576, 256>>>(B5, B5, ln_out_w, ln_out_b);

    pw128_kernel<<<gpx, 256>>>(B5, WT1, B1, 1);
    dw3_kernel<<<dwBlocks, 256>>>(B1, f1_dw, B2, nullptr);
    pw128_kernel<<<gpx, 256>>>(B5, WT2, B1, 1);
    dw3_kernel<<<dwBlocks, 256>>>(B1, f2_dw, B3, nullptr);

    foutpool_kernel<<<gpx, 256>>>(B2, B3);
    gate_kernel<<<4, 128>>>(gw1, gb1, gw2, gb2, out);
}

// round 3
// speedup vs baseline: 1.2783x; 1.0925x over previous
#include <cuda_runtime.h>
#include <math.h>

#define Bn 4
#define Cn 128
#define Hn 192
#define Wn 192
#define HW 36864
#define CHW 4718592
#define TOT 18874368
#define NH 2
#define HD 64
#define KSPLIT 144
#define CHUNK 256   // HW / KSPLIT

#define WS 132      // smem W row stride (floats)
#define XS 136      // smem X row stride (floats)
#define SMEM_PW ((128 * WS + 128 * XS) * 4)
#define SMEM_FP (SMEM_PW + 1024)

// ---------------- scratch (static device allocations) ----------------
__device__ float g_B0[TOT];
__device__ float g_B1[TOT];
__device__ float g_B2[TOT];
__device__ float g_B3[TOT];
__device__ float g_B4[TOT];
__device__ float g_B5[TOT];
__device__ float g_mu[Bn * HW];
__device__ float g_rs[Bn * HW];
__device__ float g_sq[1024];   // sumsq for q (0..511) and k (512..1023)
__device__ float g_S[32768];   // (b,n,64,64) raw gram
__device__ float g_A[32768];   // softmax(attn)
__device__ float g_avg[512];
__device__ float g_max[512];

__device__ __forceinline__ float gelu_f(float x){
    return 0.5f * x * (1.0f + erff(x * 0.7071067811865476f));
}

__device__ __forceinline__ void atomicMaxF(float* addr, float v){
    if (v >= 0.0f) atomicMax((int*)addr, __float_as_int(v));
    else           atomicMin((unsigned int*)addr, __float_as_uint(v));
}

// ---------------- tf32 mma helpers ----------------
__device__ __forceinline__ unsigned f2tf32(float x){
    unsigned r; asm("cvt.rna.tf32.f32 %0, %1;" : "=r"(r) : "f"(x)); return r;
}
__device__ __forceinline__ void split_tf32(float x, unsigned& hi, unsigned& lo){
    hi = f2tf32(x);
    lo = f2tf32(x - __uint_as_float(hi));
}
__device__ __forceinline__ void mma_tf32(float* c, const unsigned* a, const unsigned* b){
    asm volatile("mma.sync.aligned.m16n8k8.row.col.f32.tf32.tf32.f32 "
        "{%0,%1,%2,%3}, {%4,%5,%6,%7}, {%8,%9}, {%0,%1,%2,%3};"
        : "+f"(c[0]), "+f"(c[1]), "+f"(c[2]), "+f"(c[3])
        : "r"(a[0]), "r"(a[1]), "r"(a[2]), "r"(a[3]), "r"(b[0]), "r"(b[1]));
}

__global__ void init_kernel(){
    int i = blockIdx.x * 256 + threadIdx.x;
    if (i < 32768) g_S[i] = 0.0f;
    if (i < 1024) g_sq[i] = 0.0f;
    if (i < 512){ g_avg[i] = 0.0f; g_max[i] = __int_as_float(0xff800000); }
}

// ---------------- LN stats per pixel ----------------
__global__ void lnstats_kernel(const float* __restrict__ X){
    int pix = blockIdx.x * 256 + threadIdx.x;     // B*HW threads
    int b = pix / HW, p = pix - b * HW;
    const float* xb = X + b * CHW + p;
    float s = 0.f, s2 = 0.f;
    #pragma unroll 8
    for (int c = 0; c < Cn; c++){ float v = xb[c * HW]; s += v; s2 += v * v; }
    float mean = s * (1.0f / Cn);
    float var  = s2 * (1.0f / Cn) - mean * mean;
    g_mu[pix] = mean;
    g_rs[pix] = rsqrtf(var + 1e-5f);
}

// ---- fused multi-set 1x1 conv (tf32 mma, 3-term split), LN applied on load ----
// Y_s[co][px] = sum_ci W_s[co][ci] * LN(X)[ci][px]
__global__ void __launch_bounds__(256) pwmulti_kernel(
    const float* __restrict__ X,
    const float* __restrict__ lnw, const float* __restrict__ lnb,
    const float* __restrict__ W0, const float* __restrict__ W1, const float* __restrict__ W2,
    float* __restrict__ Y0, float* __restrict__ Y1, float* __restrict__ Y2,
    int nsets, int doGelu)
{
    extern __shared__ float sm[];
    float* sW = sm;
    float* sX = sm + 128 * WS;
    int b = blockIdx.y, px0 = blockIdx.x * 128;
    int tid = threadIdx.x, lane = tid & 31, wid = tid >> 5;
    int grp = lane >> 2, tig = lane & 3;
    int mtile = (wid >> 2) * 64, ntile = (wid & 3) * 32;

    // ---- X tile load with LayerNorm ----
    {
        int colf = (tid & 31) * 4;
        float4 mu4 = *(const float4*)(g_mu + b * HW + px0 + colf);
        float4 rs4 = *(const float4*)(g_rs + b * HW + px0 + colf);
        const float* Xb = X + b * CHW + px0 + colf;
        #pragma unroll
        for (int i = 0; i < 16; i++){
            int row = (tid >> 5) + i * 8;
            float4 v = *(const float4*)(Xb + row * HW);
            float wv = lnw[row], bv = lnb[row];
            v.x = (v.x - mu4.x) * rs4.x * wv + bv;
            v.y = (v.y - mu4.y) * rs4.y * wv + bv;
            v.z = (v.z - mu4.z) * rs4.z * wv + bv;
            v.w = (v.w - mu4.w) * rs4.w * wv + bv;
            *(float4*)&sX[row * XS + colf] = v;
        }
    }

    const float* Wp[3] = {W0, W1, W2};
    float*       Yp[3] = {Y0, Y1, Y2};

    for (int s = 0; s < nsets; s++){
        __syncthreads();
        #pragma unroll
        for (int i = 0; i < 16; i++){
            int idx = tid + i * 256;
            int row = idx >> 5, colf = (idx & 31) * 4;
            *(float4*)&sW[row * WS + colf] = *(const float4*)(Wp[s] + row * 128 + colf);
        }
        __syncthreads();

        float acc[4][4][4] = {};
        for (int k0 = 0; k0 < 128; k0 += 8){
            unsigned ahi[4][4], alo[4][4];
            #pragma unroll
            for (int ma = 0; ma < 4; ma++){
                int mb = mtile + ma * 16;
                float a0 = sW[(mb + grp) * WS + k0 + tig];
                float a1 = sW[(mb + grp + 8) * WS + k0 + tig];
                float a2 = sW[(mb + grp) * WS + k0 + tig + 4];
                float a3 = sW[(mb + grp + 8) * WS + k0 + tig + 4];
                split_tf32(a0, ahi[ma][0], alo[ma][0]);
                split_tf32(a1, ahi[ma][1], alo[ma][1]);
                split_tf32(a2, ahi[ma][2], alo[ma][2]);
                split_tf32(a3, ahi[ma][3], alo[ma][3]);
            }
            #pragma unroll
            for (int na = 0; na < 4; na++){
                int nb_ = ntile + na * 8 + grp;
                float b0 = sX[(k0 + tig) * XS + nb_];
                float b1 = sX[(k0 + tig + 4) * XS + nb_];
                unsigned bh[2], bl[2];
                split_tf32(b0, bh[0], bl[0]);
                split_tf32(b1, bh[1], bl[1]);
                #pragma unroll
                for (int ma = 0; ma < 4; ma++){
                    mma_tf32(acc[ma][na], ahi[ma], bh);
                    mma_tf32(acc[ma][na], ahi[ma], bl);
                    mma_tf32(acc[ma][na], alo[ma], bh);
                }
            }
        }

        float* Yb = Yp[s] + b * CHW + px0;
        #pragma unroll
        for (int ma = 0; ma < 4; ma++){
            #pragma unroll
            for (int na = 0; na < 4; na++){
                int co = mtile + ma * 16 + grp;
                int px = ntile + na * 8 + tig * 2;
                float2 v0 = make_float2(acc[ma][na][0], acc[ma][na][1]);
                float2 v1 = make_float2(acc[ma][na][2], acc[ma][na][3]);
                if (doGelu){
                    v0.x = gelu_f(v0.x); v0.y = gelu_f(v0.y);
                    v1.x = gelu_f(v1.x); v1.y = gelu_f(v1.y);
                }
                *(float2*)&Yb[co * HW + px]       = v0;
                *(float2*)&Yb[(co + 8) * HW + px] = v1;
            }
        }
    }
}

// ---- fused f_out conv (K=256, tf32 mma) + gelu(load) + avg/max pooling ----
__global__ void __launch_bounds__(256) foutpool_kernel(
    const float* __restrict__ O1, const float* __restrict__ O2,
    const float* __restrict__ Wf)
{
    extern __shared__ float sm[];
    float* sW = sm;
    float* sX = sm + 128 * WS;
    float* ssum = sm + 128 * WS + 128 * XS;
    float* smax = ssum + 128;
    int b = blockIdx.y, px0 = blockIdx.x * 128;
    int tid = threadIdx.x, lane = tid & 31, wid = tid >> 5;
    int grp = lane >> 2, tig = lane & 3;
    int mtile = (wid >> 2) * 64, ntile = (wid & 3) * 32;

    if (tid < 128){ ssum[tid] = 0.f; smax[tid] = __int_as_float(0xff800000); }

    float acc[4][4][4] = {};
    for (int ph = 0; ph < 2; ph++){
        const float* src = (ph == 0) ? O1 : O2;
        __syncthreads();
        #pragma unroll
        for (int i = 0; i < 16; i++){
            int idx = tid + i * 256;
            int row = idx >> 5, colf = (idx & 31) * 4;
            *(float4*)&sW[row * WS + colf] = *(const float4*)(Wf + row * 256 + ph * 128 + colf);
            float4 v = *(const float4*)(src + b * CHW + row * HW + px0 + colf);
            v.x = gelu_f(v.x); v.y = gelu_f(v.y); v.z = gelu_f(v.z); v.w = gelu_f(v.w);
            *(float4*)&sX[row * XS + colf] = v;
        }
        __syncthreads();

        for (int k0 = 0; k0 < 128; k0 += 8){
            unsigned ahi[4][4], alo[4][4];
            #pragma unroll
            for (int ma = 0; ma < 4; ma++){
                int mb = mtile + ma * 16;
                float a0 = sW[(mb + grp) * WS + k0 + tig];
                float a1 = sW[(mb + grp + 8) * WS + k0 + tig];
                float a2 = sW[(mb + grp) * WS + k0 + tig + 4];
                float a3 = sW[(mb + grp + 8) * WS + k0 + tig + 4];
                split_tf32(a0, ahi[ma][0], alo[ma][0]);
                split_tf32(a1, ahi[ma][1], alo[ma][1]);
                split_tf32(a2, ahi[ma][2], alo[ma][2]);
                split_tf32(a3, ahi[ma][3], alo[ma][3]);
            }
            #pragma unroll
            for (int na = 0; na < 4; na++){
                int nb_ = ntile + na * 8 + grp;
                float b0 = sX[(k0 + tig) * XS + nb_];
                float b1 = sX[(k0 + tig + 4) * XS + nb_];
                unsigned bh[2], bl[2];
                split_tf32(b0, bh[0], bl[0]);
                split_tf32(b1, bh[1], bl[1]);
                #pragma unroll
                for (int ma = 0; ma < 4; ma++){
                    mma_tf32(acc[ma][na], ahi[ma], bh);
                    mma_tf32(acc[ma][na], ahi[ma], bl);
                    mma_tf32(acc[ma][na], alo[ma], bh);
                }
            }
        }
    }
    __syncthreads();

    // pooling epilogue: sum/max over the 32 px of this warp's tile per co row
    #pragma unroll
    for (int ma = 0; ma < 4; ma++){
        float s0 = 0.f, s1 = 0.f;
        float m0 = __int_as_float(0xff800000), m1 = m0;
        #pragma unroll
        for (int na = 0; na < 4; na++){
            s0 += acc[ma][na][0] + acc[ma][na][1];
            s1 += acc[ma][na][2] + acc[ma][na][3];
            m0 = fmaxf(m0, fmaxf(acc[ma][na][0], acc[ma][na][1]));
            m1 = fmaxf(m1, fmaxf(acc[ma][na][2], acc[ma][na][3]));
        }
        #pragma unroll
        for (int st = 1; st <= 2; st <<= 1){
            s0 += __shfl_xor_sync(0xffffffffu, s0, st);
            s1 += __shfl_xor_sync(0xffffffffu, s1, st);
            m0 = fmaxf(m0, __shfl_xor_sync(0xffffffffu, m0, st));
            m1 = fmaxf(m1, __shfl_xor_sync(0xffffffffu, m1, st));
        }
        if (tig == 0){
            int co = mtile + ma * 16 + grp;
            atomicAdd(&ssum[co], s0);     atomicMaxF(&smax[co], m0);
            atomicAdd(&ssum[co + 8], s1); atomicMaxF(&smax[co + 8], m1);
        }
    }
    __syncthreads();
    if (tid < 128){
        atomicAdd(&g_avg[b * 128 + tid], ssum[tid]);
        atomicMaxF(&g_max[b * 128 + tid], smax[tid]);
    }
}

// ---------------- depthwise 3x3 pad 1, 4px/thread, optional fused sumsq ----------------
__global__ void dw3_kernel(const float* __restrict__ X, const float* __restrict__ Wd,
                           float* __restrict__ Y, float* __restrict__ sq){
    int idx = blockIdx.x * 256 + threadIdx.x;     // TOT/4 threads
    int plane = idx / (HW / 4);                   // b*128 + c
    int pin   = (idx - plane * (HW / 4)) * 4;
    int c = plane & 127;
    int h = pin / Wn, w = pin - h * Wn;
    const float* xp = X + plane * HW;
    const float* wd = Wd + c * 9;
    float o0 = 0.f, o1 = 0.f, o2 = 0.f, o3 = 0.f;
    #pragma unroll
    for (int dy = -1; dy <= 1; dy++){
        int hh = h + dy;
        if ((unsigned)hh >= Hn) continue;
        const float* r = xp + hh * Wn + w;
        float4 c4 = *(const float4*)r;
        float lm = (w > 0)        ? r[-1] : 0.f;
        float rp = (w + 4 < Wn)   ? r[4]  : 0.f;
        float k0 = wd[(dy + 1) * 3 + 0], k1 = wd[(dy + 1) * 3 + 1], k2 = wd[(dy + 1) * 3 + 2];
        o0 = fmaf(lm,   k0, fmaf(c4.x, k1, fmaf(c4.y, k2, o0)));
        o1 = fmaf(c4.x, k0, fmaf(c4.y, k1, fmaf(c4.z, k2, o1)));
        o2 = fmaf(c4.y, k0, fmaf(c4.z, k1, fmaf(c4.w, k2, o2)));
        o3 = fmaf(c4.z, k0, fmaf(c4.w, k1, fmaf(rp,   k2, o3)));
    }
    float4 o; o.x = o0; o.y = o1; o.z = o2; o.w = o3;
    *(float4*)&Y[plane * HW + pin] = o;
    if (sq){
        float s = o0*o0 + o1*o1 + o2*o2 + o3*o3;
        #pragma unroll
        for (int st = 16; st > 0; st >>= 1)
            s += __shfl_down_sync(0xffffffffu, s, st);
        if ((threadIdx.x & 31) == 0) atomicAdd(&sq[plane], s);
    }
}

// ---------------- raw gram S += q k^T, split-K over pixels ----------------
__global__ void gram_kernel(const float* __restrict__ Q, const float* __restrict__ K){
    __shared__ __align__(16) float sq[8][64];
    __shared__ __align__(16) float sk[8][64];
    int bn = blockIdx.y;
    int b = bn >> 1, n = bn & 1;
    const float* Qb = Q + b * CHW + n * HD * HW;
    const float* Kb = K + b * CHW + n * HD * HW;
    int p0 = blockIdx.x * CHUNK;
    int t  = threadIdx.x;
    int c0 = (t >> 4) * 8;
    int d0 = (t & 15) * 4;
    int lc = t >> 1;
    int lp = (t & 1) * 4;
    float acc[8][4] = {};
    for (int p = p0; p < p0 + CHUNK; p += 8){
        float4 qa = *(const float4*)(Qb + lc * HW + p + lp);
        float4 ka = *(const float4*)(Kb + lc * HW + p + lp);
        __syncthreads();
        sq[lp+0][lc]=qa.x; sq[lp+1][lc]=qa.y; sq[lp+2][lc]=qa.z; sq[lp+3][lc]=qa.w;
        sk[lp+0][lc]=ka.x; sk[lp+1][lc]=ka.y; sk[lp+2][lc]=ka.z; sk[lp+3][lc]=ka.w;
        __syncthreads();
        #pragma unroll
        for (int pp = 0; pp < 8; pp++){
            float4 w0 = *(const float4*)&sq[pp][c0];
            float4 w1 = *(const float4*)&sq[pp][c0 + 4];
            float4 xr = *(const float4*)&sk[pp][d0];
            float wr[8] = {w0.x,w0.y,w0.z,w0.w,w1.x,w1.y,w1.z,w1.w};
            float xv[4] = {xr.x,xr.y,xr.z,xr.w};
            #pragma unroll
            for (int i = 0; i < 8; i++)
                #pragma unroll
                for (int j = 0; j < 4; j++)
                    acc[i][j] = fmaf(wr[i], xv[j], acc[i][j]);
        }
    }
    float* Sp = g_S + bn * 4096;
    #pragma unroll
    for (int i = 0; i < 8; i++)
        #pragma unroll
        for (int j = 0; j < 4; j++)
            atomicAdd(&Sp[(c0 + i) * 64 + d0 + j], acc[i][j]);
}

// ---------------- finalize attn (write attn_weight) + softmax ----------------
__global__ void attnfin_kernel(const float* __restrict__ scale, float* __restrict__ outAttn){
    int row = blockIdx.x;
    int d   = threadIdx.x;
    int b = row >> 7;
    int r = row & 127;
    int n = r >> 6;
    float nq = fmaxf(sqrtf(g_sq[b * 128 + r]), 1e-12f);
    float nk = fmaxf(sqrtf(g_sq[512 + b * 128 + (n << 6) + d]), 1e-12f);
    float val = g_S[row * 64 + d] / (nq * nk) * scale[n];
    outAttn[row * 64 + d] = val;
    __shared__ float sm[64];
    sm[d] = val; __syncthreads();
    for (int st = 32; st > 0; st >>= 1){ if (d < st) sm[d] = fmaxf(sm[d], sm[d + st]); __syncthreads(); }
    float mx = sm[0]; __syncthreads();
    float e = expf(val - mx);
    sm[d] = e; __syncthreads();
    for (int st = 32; st > 0; st >>= 1){ if (d < st) sm[d] += sm[d + st]; __syncthreads(); }
    g_A[row * 64 + d] = e / sm[0];
}

// ---------------- out = a @ v : tile 64c x 64px, K=64 ----------------
__global__ void applyav_kernel(const float* __restrict__ V, float* __restrict__ Out){
    __shared__ __align__(16) float sA[8][64];
    __shared__ __align__(16) float sV[8][64];
    int bn = blockIdx.y;
    int b = bn >> 1, n = bn & 1;
    const float* Vb = V + b * CHW + n * HD * HW;
    const float* Ab = g_A + bn * 4096;
    int px0 = blockIdx.x * 64;
    int t = threadIdx.x;
    int c0 = (t >> 4) * 8, pl = (t & 15) * 4;
    int lc = t >> 1,      ld = (t & 1) * 4;
    int vk = t >> 4,      vp = (t & 15) * 4;
    float acc[8][4] = {};
    for (int dd = 0; dd < 64; dd += 8){
        float4 a4 = *(const float4*)(Ab + lc * 64 + dd + ld);
        float4 v4 = *(const float4*)(Vb + (dd + vk) * HW + px0 + vp);
        __syncthreads();
        sA[ld+0][lc]=a4.x; sA[ld+1][lc]=a4.y; sA[ld+2][lc]=a4.z; sA[ld+3][lc]=a4.w;
        *(float4*)&sV[vk][vp] = v4;
        __syncthreads();
        #pragma unroll
        for (int pp = 0; pp < 8; pp++){
            float4 a0 = *(const float4*)&sA[pp][c0];
            float4 a1 = *(const float4*)&sA[pp][c0 + 4];
            float4 vr = *(const float4*)&sV[pp][pl];
            float ar[8] = {a0.x,a0.y,a0.z,a0.w,a1.x,a1.y,a1.z,a1.w};
            float vv[4] = {vr.x,vr.y,vr.z,vr.w};
            #pragma unroll
            for (int i = 0; i < 8; i++)
                #pragma unroll
                for (int j = 0; j < 4; j++)
                    acc[i][j] = fmaf(ar[i], vv[j], acc[i][j]);
        }
    }
    float* Ob = Out + b * CHW + n * HD * HW + px0;
    #pragma unroll
    for (int i = 0; i < 8; i++){
        float4 o; o.x = acc[i][0]; o.y = acc[i][1]; o.z = acc[i][2]; o.w = acc[i][3];
        *(float4*)&Ob[(c0 + i) * HW + pl] = o;
    }
}

// ---------------- channel gate MLP -> sigmoid -> spec_score ----------------
__global__ void gate_kernel(const float* __restrict__ w1, const float* __restrict__ b1,
                            const float* __restrict__ w2, const float* __restrict__ b2,
                            float* __restrict__ out){
    int b = blockIdx.x;
    int c = threadIdx.x;
    __shared__ float avg[128], mx[128], ha[8], hm[8];
    avg[c] = g_avg[b * 128 + c] * (1.0f / HW);
    mx[c]  = g_max[b * 128 + c];
    __syncthreads();
    if (c < 8){
        float sa = b1[c], sm_ = b1[c];
        for (int j = 0; j < 128; j++){
            sa  += w1[c * 128 + j] * avg[j];
            sm_ += w1[c * 128 + j] * mx[j];
        }
        ha[c] = fmaxf(sa, 0.f);
        hm[c] = fmaxf(sm_, 0.f);
    }
    __syncthreads();
    float z = 2.0f * b2[c];
    for (int j = 0; j < 8; j++) z += (ha[j] + hm[j]) * w2[c * 8 + j];
    out[b * 128 + c] = 1.0f / (1.0f + expf(-z));
}

// ---------------- launch ----------------
extern "C" void kernel_launch(void* const* d_in, const int* in_sizes, int n_in,
                              void* d_out, int out_size){
    const float* x        = (const float*)d_in[0];
    const float* ln_in_w  = (const float*)d_in[1];
    const float* ln_in_b  = (const float*)d_in[2];
    const float* wq_pw    = (const float*)d_in[3];
    const float* wq_dw    = (const float*)d_in[4];
    const float* wk_pw    = (const float*)d_in[5];
    const float* wk_dw    = (const float*)d_in[6];
    const float* wv_pw    = (const float*)d_in[7];
    const float* wv_dw    = (const float*)d_in[8];
    const float* scale    = (const float*)d_in[9];
    const float* ln_out_w = (const float*)d_in[10];
    const float* ln_out_b = (const float*)d_in[11];
    const float* f1_pw    = (const float*)d_in[12];
    const float* f1_dw    = (const float*)d_in[13];
    const float* f2_pw    = (const float*)d_in[14];
    const float* f2_dw    = (const float*)d_in[15];
    const float* f_out    = (const float*)d_in[16];
    const float* gw1      = (const float*)d_in[17];
    const float* gb1      = (const float*)d_in[18];
    const float* gw2      = (const float*)d_in[19];
    const float* gb2      = (const float*)d_in[20];
    float* out = (float*)d_out;

    static int attrDone = 0;
    if (!attrDone){
        cudaFuncSetAttribute(pwmulti_kernel,  cudaFuncAttributeMaxDynamicSharedMemorySize, SMEM_PW);
        cudaFuncSetAttribute(foutpool_kernel, cudaFuncAttributeMaxDynamicSharedMemorySize, SMEM_FP);
        attrDone = 1;
    }

    void *p;
    float *B0,*B1,*B2,*B3,*B4,*B5,*SQ;
    cudaGetSymbolAddress(&p, g_B0);  B0  = (float*)p;
    cudaGetSymbolAddress(&p, g_B1);  B1  = (float*)p;
    cudaGetSymbolAddress(&p, g_B2);  B2  = (float*)p;
    cudaGetSymbolAddress(&p, g_B3);  B3  = (float*)p;
    cudaGetSymbolAddress(&p, g_B4);  B4  = (float*)p;
    cudaGetSymbolAddress(&p, g_B5);  B5  = (float*)p;
    cudaGetSymbolAddress(&p, g_sq);  SQ  = (float*)p;

    dim3 gpx(288, Bn);
    const int dwBlocks = TOT / 4 / 256;

    init_kernel<<<128, 256>>>();

    // -- attention half --
    lnstats_kernel<<<576, 256>>>(x);
    pwmulti_kernel<<<gpx, 256, SMEM_PW>>>(x, ln_in_w, ln_in_b,
                                          wq_pw, wk_pw, wv_pw,
                                          B0, B1, B5, 3, 0);
    dw3_kernel<<<dwBlocks, 256>>>(B0, wq_dw, B2, SQ);
    dw3_kernel<<<dwBlocks, 256>>>(B1, wk_dw, B3, SQ + 512);
    dw3_kernel<<<dwBlocks, 256>>>(B5, wv_dw, B4, nullptr);

    gram_kernel<<<dim3(KSPLIT, 8), 128>>>(B2, B3);
    attnfin_kernel<<<512, 64>>>(scale, out + 512);
    applyav_kernel<<<dim3(576, 8), 128>>>(B4, B0);

    // -- FFN half --
    lnstats_kernel<<<576, 256>>>(B0);
    pwmulti_kernel<<<gpx, 256, SMEM_PW>>>(B0, ln_out_w, ln_out_b,
                                          f1_pw, f2_pw, nullptr,
                                          B1, B5, nullptr, 2, 1);
    dw3_kernel<<<dwBlocks, 256>>>(B1, f1_dw, B2, nullptr);
    dw3_kernel<<<dwBlocks, 256>>>(B5, f2_dw, B3, nullptr);

    foutpool_kernel<<<gpx, 256, SMEM_FP>>>(B2, B3, f_out);
    gate_kernel<<<4, 128>>>(gw1, gb1, gw2, gb2, out);
}

// round 4
// speedup vs baseline: 1.8630x; 1.4574x over previous
#include <cuda_runtime.h>
#include <cuda_bf16.h>
#include <math.h>

#define Bn 4
#define Cn 128
#define Hn 192
#define Wn 192
#define HW 36864
#define CHW 4718592
#define TOT 18874368
#define NH 2
#define HD 64
#define KSPLIT 144
#define CHUNK 256   // HW / KSPLIT

// smem word strides (chosen for conflict-free lane->bank maps)
#define WS2 68      // W plane row stride (uint32 words), 128 rows
#define XS2 136     // X plane row stride (uint32 words), 64 kpair rows
#define WPL (128 * WS2)   // 8704 words per W plane
#define XPL (64 * XS2)    // 8704 words per X plane
#define SMEM_PW ((2 * WPL + 2 * XPL) * 4)     // 139264 B
#define SMEM_FP (SMEM_PW + 1024)

// ---------------- scratch (static device allocations) ----------------
__device__ float g_B0[TOT];
__device__ float g_B1[TOT];
__device__ float g_B2[TOT];
__device__ float g_B3[TOT];
__device__ float g_B4[TOT];
__device__ float g_B5[TOT];
__device__ float g_mu[Bn * HW];
__device__ float g_rs[Bn * HW];
__device__ float g_sq[1024];   // sumsq for q (0..511) and k (512..1023)
__device__ float g_S[32768];   // (b,n,64,64) raw gram
__device__ float g_A[32768];   // softmax(attn)
__device__ float g_avg[512];
__device__ float g_max[512];

__device__ __forceinline__ float gelu_f(float x){
    return 0.5f * x * (1.0f + erff(x * 0.7071067811865476f));
}

__device__ __forceinline__ void atomicMaxF(float* addr, float v){
    if (v >= 0.0f) atomicMax((int*)addr, __float_as_int(v));
    else           atomicMin((unsigned int*)addr, __float_as_uint(v));
}

// ---------------- bf16 split helpers ----------------
// word = {hi16 = bf16(b_up), lo16 = bf16(a_lo)}  (first asm operand -> upper half)
__device__ __forceinline__ unsigned packbf2(float up, float lo){
    unsigned r;
    asm("cvt.rn.bf16x2.f32 %0, %1, %2;" : "=r"(r) : "f"(up), "f"(lo));
    return r;
}
__device__ __forceinline__ void split2(float x, float& hi, float& lo){
    hi = __bfloat162float(__float2bfloat16_rn(x));
    lo = x - hi;
}
// pack channel pair (c even = low half, c+1 = high half) into hi-word and lo-word
__device__ __forceinline__ void packpair(float xlo, float xup, unsigned& wh, unsigned& wl){
    float h0, l0, h1, l1;
    split2(xlo, h0, l0);
    split2(xup, h1, l1);
    wh = packbf2(h1, h0);
    wl = packbf2(l1, l0);
}
__device__ __forceinline__ void mma_bf16(float* c, const unsigned* a, const unsigned* b){
    asm volatile("mma.sync.aligned.m16n8k16.row.col.f32.bf16.bf16.f32 "
        "{%0,%1,%2,%3}, {%4,%5,%6,%7}, {%8,%9}, {%0,%1,%2,%3};"
        : "+f"(c[0]), "+f"(c[1]), "+f"(c[2]), "+f"(c[3])
        : "r"(a[0]), "r"(a[1]), "r"(a[2]), "r"(a[3]), "r"(b[0]), "r"(b[1]));
}

__global__ void init_kernel(){
    int i = blockIdx.x * 256 + threadIdx.x;
    if (i < 32768) g_S[i] = 0.0f;
    if (i < 1024) g_sq[i] = 0.0f;
    if (i < 512){ g_avg[i] = 0.0f; g_max[i] = __int_as_float(0xff800000); }
}

// ---------------- LN stats per pixel ----------------
__global__ void lnstats_kernel(const float* __restrict__ X){
    int pix = blockIdx.x * 256 + threadIdx.x;     // B*HW threads
    int b = pix / HW, p = pix - b * HW;
    const float* xb = X + b * CHW + p;
    float s = 0.f, s2 = 0.f;
    #pragma unroll 8
    for (int c = 0; c < Cn; c++){ float v = xb[c * HW]; s += v; s2 += v * v; }
    float mean = s * (1.0f / Cn);
    float var  = s2 * (1.0f / Cn) - mean * mean;
    g_mu[pix] = mean;
    g_rs[pix] = rsqrtf(var + 1e-5f);
}

// ---- fused multi-set 1x1 conv (bf16 3-term mma), LN applied on load ----
__global__ void __launch_bounds__(256) pwmulti_kernel(
    const float* __restrict__ X,
    const float* __restrict__ lnw, const float* __restrict__ lnb,
    const float* __restrict__ W0, const float* __restrict__ W1, const float* __restrict__ W2,
    float* __restrict__ Y0, float* __restrict__ Y1, float* __restrict__ Y2,
    int nsets, int doGelu)
{
    extern __shared__ unsigned smu[];
    unsigned* WPh = smu;
    unsigned* WPl = smu + WPL;
    unsigned* XPh = smu + 2 * WPL;
    unsigned* XPl = smu + 2 * WPL + XPL;
    int b = blockIdx.y, px0 = blockIdx.x * 128;
    int tid = threadIdx.x, lane = tid & 31, wid = tid >> 5;
    int grp = lane >> 2, tig = lane & 3;
    int mtile = (wid >> 2) * 64, ntile = (wid & 3) * 32;

    // ---- X tile load: LN + bf16 hi/lo split, packed by channel pairs ----
    #pragma unroll
    for (int i = 0; i < 8; i++){
        int idx = tid + i * 256;          // 2048 items: 64 rowpairs x 32 px-groups
        int r = idx >> 5, g = idx & 31;
        int px = g * 4;
        float4 mu4 = *(const float4*)(g_mu + b * HW + px0 + px);
        float4 rs4 = *(const float4*)(g_rs + b * HW + px0 + px);
        float4 x0 = *(const float4*)(X + b * CHW + (2 * r) * HW + px0 + px);
        float4 x1 = *(const float4*)(X + b * CHW + (2 * r + 1) * HW + px0 + px);
        float w0 = lnw[2 * r], b0 = lnb[2 * r];
        float w1 = lnw[2 * r + 1], b1 = lnb[2 * r + 1];
        float a0 = (x0.x - mu4.x) * rs4.x * w0 + b0;
        float a1 = (x0.y - mu4.y) * rs4.y * w0 + b0;
        float a2 = (x0.z - mu4.z) * rs4.z * w0 + b0;
        float a3 = (x0.w - mu4.w) * rs4.w * w0 + b0;
        float c0 = (x1.x - mu4.x) * rs4.x * w1 + b1;
        float c1 = (x1.y - mu4.y) * rs4.y * w1 + b1;
        float c2 = (x1.z - mu4.z) * rs4.z * w1 + b1;
        float c3 = (x1.w - mu4.w) * rs4.w * w1 + b1;
        uint4 vh, vl;
        packpair(a0, c0, vh.x, vl.x);
        packpair(a1, c1, vh.y, vl.y);
        packpair(a2, c2, vh.z, vl.z);
        packpair(a3, c3, vh.w, vl.w);
        *(uint4*)&XPh[r * XS2 + px] = vh;
        *(uint4*)&XPl[r * XS2 + px] = vl;
    }

    const float* Wp[3] = {W0, W1, W2};
    float*       Yp[3] = {Y0, Y1, Y2};

    for (int s = 0; s < nsets; s++){
        __syncthreads();
        #pragma unroll
        for (int i = 0; i < 16; i++){
            int idx = tid + i * 256;      // 4096 items: 128 rows x 32 quads
            int row = idx >> 5, quad = idx & 31;
            float4 v = *(const float4*)(Wp[s] + row * 128 + quad * 4);
            uint2 wh, wl;
            packpair(v.x, v.y, wh.x, wl.x);
            packpair(v.z, v.w, wh.y, wl.y);
            *(uint2*)&WPh[row * WS2 + quad * 2] = wh;
            *(uint2*)&WPl[row * WS2 + quad * 2] = wl;
        }
        __syncthreads();

        float acc[4][4][4] = {};
        #pragma unroll
        for (int ks = 0; ks < 8; ks++){
            int kp = ks * 8 + tig;
            unsigned ah[4][4], al[4][4];
            #pragma unroll
            for (int ma = 0; ma < 4; ma++){
                int r0 = (mtile + ma * 16 + grp) * WS2;
                int r1 = r0 + 8 * WS2;
                ah[ma][0] = WPh[r0 + kp];     ah[ma][1] = WPh[r1 + kp];
                ah[ma][2] = WPh[r0 + kp + 4]; ah[ma][3] = WPh[r1 + kp + 4];
                al[ma][0] = WPl[r0 + kp];     al[ma][1] = WPl[r1 + kp];
                al[ma][2] = WPl[r0 + kp + 4]; al[ma][3] = WPl[r1 + kp + 4];
            }
            #pragma unroll
            for (int na = 0; na < 4; na++){
                int col = ntile + na * 8 + grp;
                unsigned bh[2], bl[2];
                bh[0] = XPh[kp * XS2 + col]; bh[1] = XPh[(kp + 4) * XS2 + col];
                bl[0] = XPl[kp * XS2 + col]; bl[1] = XPl[(kp + 4) * XS2 + col];
                #pragma unroll
                for (int ma = 0; ma < 4; ma++){
                    mma_bf16(acc[ma][na], ah[ma], bh);
                    mma_bf16(acc[ma][na], ah[ma], bl);
                    mma_bf16(acc[ma][na], al[ma], bh);
                }
            }
        }

        float* Yb = Yp[s] + b * CHW + px0;
        #pragma unroll
        for (int ma = 0; ma < 4; ma++){
            #pragma unroll
            for (int na = 0; na < 4; na++){
                int co = mtile + ma * 16 + grp;
                int px = ntile + na * 8 + tig * 2;
                float2 v0 = make_float2(acc[ma][na][0], acc[ma][na][1]);
                float2 v1 = make_float2(acc[ma][na][2], acc[ma][na][3]);
                if (doGelu){
                    v0.x = gelu_f(v0.x); v0.y = gelu_f(v0.y);
                    v1.x = gelu_f(v1.x); v1.y = gelu_f(v1.y);
                }
                *(float2*)&Yb[co * HW + px]       = v0;
                *(float2*)&Yb[(co + 8) * HW + px] = v1;
            }
        }
    }
}

// ---- fused f_out conv (K=256, bf16 mma) + gelu(load) + avg/max pooling ----
__global__ void __launch_bounds__(256) foutpool_kernel(
    const float* __restrict__ O1, const float* __restrict__ O2,
    const float* __restrict__ Wf)
{
    extern __shared__ unsigned smu[];
    unsigned* WPh = smu;
    unsigned* WPl = smu + WPL;
    unsigned* XPh = smu + 2 * WPL;
    unsigned* XPl = smu + 2 * WPL + XPL;
    float* ssum = (float*)(smu + 2 * WPL + 2 * XPL);
    float* smax = ssum + 128;
    int b = blockIdx.y, px0 = blockIdx.x * 128;
    int tid = threadIdx.x, lane = tid & 31, wid = tid >> 5;
    int grp = lane >> 2, tig = lane & 3;
    int mtile = (wid >> 2) * 64, ntile = (wid & 3) * 32;

    if (tid < 128){ ssum[tid] = 0.f; smax[tid] = __int_as_float(0xff800000); }

    float acc[4][4][4] = {};
    for (int ph = 0; ph < 2; ph++){
        const float* src = (ph == 0) ? O1 : O2;
        __syncthreads();
        #pragma unroll
        for (int i = 0; i < 8; i++){
            int idx = tid + i * 256;
            int r = idx >> 5, g = idx & 31;
            int px = g * 4;
            float4 x0 = *(const float4*)(src + b * CHW + (2 * r) * HW + px0 + px);
            float4 x1 = *(const float4*)(src + b * CHW + (2 * r + 1) * HW + px0 + px);
            x0.x = gelu_f(x0.x); x0.y = gelu_f(x0.y); x0.z = gelu_f(x0.z); x0.w = gelu_f(x0.w);
            x1.x = gelu_f(x1.x); x1.y = gelu_f(x1.y); x1.z = gelu_f(x1.z); x1.w = gelu_f(x1.w);
            uint4 vh, vl;
            packpair(x0.x, x1.x, vh.x, vl.x);
            packpair(x0.y, x1.y, vh.y, vl.y);
            packpair(x0.z, x1.z, vh.z, vl.z);
            packpair(x0.w, x1.w, vh.w, vl.w);
            *(uint4*)&XPh[r * XS2 + px] = vh;
            *(uint4*)&XPl[r * XS2 + px] = vl;
        }
        #pragma unroll
        for (int i = 0; i < 16; i++){
            int idx = tid + i * 256;
            int row = idx >> 5, quad = idx & 31;
            float4 v = *(const float4*)(Wf + row * 256 + ph * 128 + quad * 4);
            uint2 wh, wl;
            packpair(v.x, v.y, wh.x, wl.x);
            packpair(v.z, v.w, wh.y, wl.y);
            *(uint2*)&WPh[row * WS2 + quad * 2] = wh;
            *(uint2*)&WPl[row * WS2 + quad * 2] = wl;
        }
        __syncthreads();

        #pragma unroll
        for (int ks = 0; ks < 8; ks++){
            int kp = ks * 8 + tig;
            unsigned ah[4][4], al[4][4];
            #pragma unroll
            for (int ma = 0; ma < 4; ma++){
                int r0 = (mtile + ma * 16 + grp) * WS2;
                int r1 = r0 + 8 * WS2;
                ah[ma][0] = WPh[r0 + kp];     ah[ma][1] = WPh[r1 + kp];
                ah[ma][2] = WPh[r0 + kp + 4]; ah[ma][3] = WPh[r1 + kp + 4];
                al[ma][0] = WPl[r0 + kp];     al[ma][1] = WPl[r1 + kp];
                al[ma][2] = WPl[r0 + kp + 4]; al[ma][3] = WPl[r1 + kp + 4];
            }
            #pragma unroll
            for (int na = 0; na < 4; na++){
                int col = ntile + na * 8 + grp;
                unsigned bh[2], bl[2];
                bh[0] = XPh[kp * XS2 + col]; bh[1] = XPh[(kp + 4) * XS2 + col];
                bl[0] = XPl[kp * XS2 + col]; bl[1] = XPl[(kp + 4) * XS2 + col];
                #pragma unroll
                for (int ma = 0; ma < 4; ma++){
                    mma_bf16(acc[ma][na], ah[ma], bh);
                    mma_bf16(acc[ma][na], ah[ma], bl);
                    mma_bf16(acc[ma][na], al[ma], bh);
                }
            }
        }
    }
    __syncthreads();

    #pragma unroll
    for (int ma = 0; ma < 4; ma++){
        float s0 = 0.f, s1 = 0.f;
        float m0 = __int_as_float(0xff800000), m1 = m0;
        #pragma unroll
        for (int na = 0; na < 4; na++){
            s0 += acc[ma][na][0] + acc[ma][na][1];
            s1 += acc[ma][na][2] + acc[ma][na][3];
            m0 = fmaxf(m0, fmaxf(acc[ma][na][0], acc[ma][na][1]));
            m1 = fmaxf(m1, fmaxf(acc[ma][na][2], acc[ma][na][3]));
        }
        #pragma unroll
        for (int st = 1; st <= 2; st <<= 1){
            s0 += __shfl_xor_sync(0xffffffffu, s0, st);
            s1 += __shfl_xor_sync(0xffffffffu, s1, st);
            m0 = fmaxf(m0, __shfl_xor_sync(0xffffffffu, m0, st));
            m1 = fmaxf(m1, __shfl_xor_sync(0xffffffffu, m1, st));
        }
        if (tig == 0){
            int co = mtile + ma * 16 + grp;
            atomicAdd(&ssum[co], s0);     atomicMaxF(&smax[co], m0);
            atomicAdd(&ssum[co + 8], s1); atomicMaxF(&smax[co + 8], m1);
        }
    }
    __syncthreads();
    if (tid < 128){
        atomicAdd(&g_avg[b * 128 + tid], ssum[tid]);
        atomicMaxF(&g_max[b * 128 + tid], smax[tid]);
    }
}

// ---------------- depthwise 3x3 pad 1: 8px x 2rows per thread ----------------
__global__ void dw3_kernel(const float* __restrict__ X, const float* __restrict__ Wd,
                           float* __restrict__ Y, float* __restrict__ sq){
    int idx = blockIdx.x * 256 + threadIdx.x;     // 512 planes * 2304 threads
    int plane = idx / 2304;
    int r = idx - plane * 2304;
    int hp = r / 24, wb = r - hp * 24;
    int h = hp * 2, w = wb * 8;
    int c = plane & 127;
    const float* xp = X + plane * HW;
    const float* wdp = Wd + c * 9;
    float wd9[9];
    #pragma unroll
    for (int i = 0; i < 9; i++) wd9[i] = wdp[i];

    float ld[4][10];
    #pragma unroll
    for (int rr = 0; rr < 4; rr++){
        int hh = h - 1 + rr;
        if ((unsigned)hh < Hn){
            const float* rp_ = xp + hh * Wn + w;
            float4 a = *(const float4*)rp_;
            float4 bq = *(const float4*)(rp_ + 4);
            ld[rr][0] = (w > 0) ? rp_[-1] : 0.f;
            ld[rr][1] = a.x; ld[rr][2] = a.y; ld[rr][3] = a.z; ld[rr][4] = a.w;
            ld[rr][5] = bq.x; ld[rr][6] = bq.y; ld[rr][7] = bq.z; ld[rr][8] = bq.w;
            ld[rr][9] = (w + 8 < Wn) ? rp_[8] : 0.f;
        } else {
            #pragma unroll
            for (int j = 0; j < 10; j++) ld[rr][j] = 0.f;
        }
    }
    float o[2][8];
    #pragma unroll
    for (int orow = 0; orow < 2; orow++)
        #pragma unroll
        for (int j = 0; j < 8; j++) o[orow][j] = 0.f;
    #pragma unroll
    for (int orow = 0; orow < 2; orow++){
        #pragma unroll
        for (int t = 0; t < 3; t++){
            float k0 = wd9[t * 3 + 0], k1 = wd9[t * 3 + 1], k2 = wd9[t * 3 + 2];
            #pragma unroll
            for (int j = 0; j < 8; j++)
                o[orow][j] = fmaf(ld[orow + t][j], k0,
                             fmaf(ld[orow + t][j + 1], k1,
                             fmaf(ld[orow + t][j + 2], k2, o[orow][j])));
        }
    }
    #pragma unroll
    for (int orow = 0; orow < 2; orow++){
        float4 v0, v1;
        v0.x = o[orow][0]; v0.y = o[orow][1]; v0.z = o[orow][2]; v0.w = o[orow][3];
        v1.x = o[orow][4]; v1.y = o[orow][5]; v1.z = o[orow][6]; v1.w = o[orow][7];
        *(float4*)&Y[plane * HW + (h + orow) * Wn + w]     = v0;
        *(float4*)&Y[plane * HW + (h + orow) * Wn + w + 4] = v1;
    }
    if (sq){
        float s = 0.f;
        #pragma unroll
        for (int orow = 0; orow < 2; orow++)
            #pragma unroll
            for (int j = 0; j < 8; j++) s += o[orow][j] * o[orow][j];
        #pragma unroll
        for (int st = 16; st > 0; st >>= 1)
            s += __shfl_down_sync(0xffffffffu, s, st);
        if ((threadIdx.x & 31) == 0) atomicAdd(&sq[plane], s);
    }
}

// ---------------- raw gram S += q k^T, split-K over pixels ----------------
__global__ void gram_kernel(const float* __restrict__ Q, const float* __restrict__ K){
    __shared__ __align__(16) float sq[8][64];
    __shared__ __align__(16) float sk[8][64];
    int bn = blockIdx.y;
    int b = bn >> 1, n = bn & 1;
    const float* Qb = Q + b * CHW + n * HD * HW;
    const float* Kb = K + b * CHW + n * HD * HW;
    int p0 = blockIdx.x * CHUNK;
    int t  = threadIdx.x;
    int c0 = (t >> 4) * 8;
    int d0 = (t & 15) * 4;
    int lc = t >> 1;
    int lp = (t & 1) * 4;
    float acc[8][4] = {};
    for (int p = p0; p < p0 + CHUNK; p += 8){
        float4 qa = *(const float4*)(Qb + lc * HW + p + lp);
        float4 ka = *(const float4*)(Kb + lc * HW + p + lp);
        __syncthreads();
        sq[lp+0][lc]=qa.x; sq[lp+1][lc]=qa.y; sq[lp+2][lc]=qa.z; sq[lp+3][lc]=qa.w;
        sk[lp+0][lc]=ka.x; sk[lp+1][lc]=ka.y; sk[lp+2][lc]=ka.z; sk[lp+3][lc]=ka.w;
        __syncthreads();
        #pragma unroll
        for (int pp = 0; pp < 8; pp++){
            float4 w0 = *(const float4*)&sq[pp][c0];
            float4 w1 = *(const float4*)&sq[pp][c0 + 4];
            float4 xr = *(const float4*)&sk[pp][d0];
            float wr[8] = {w0.x,w0.y,w0.z,w0.w,w1.x,w1.y,w1.z,w1.w};
            float xv[4] = {xr.x,xr.y,xr.z,xr.w};
            #pragma unroll
            for (int i = 0; i < 8; i++)
                #pragma unroll
                for (int j = 0; j < 4; j++)
                    acc[i][j] = fmaf(wr[i], xv[j], acc[i][j]);
        }
    }
    float* Sp = g_S + bn * 4096;
    #pragma unroll
    for (int i = 0; i < 8; i++)
        #pragma unroll
        for (int j = 0; j < 4; j++)
            atomicAdd(&Sp[(c0 + i) * 64 + d0 + j], acc[i][j]);
}

// ---------------- finalize attn (write attn_weight) + softmax ----------------
__global__ void attnfin_kernel(const float* __restrict__ scale, float* __restrict__ outAttn){
    int row = blockIdx.x;
    int d   = threadIdx.x;
    int b = row >> 7;
    int r = row & 127;
    int n = r >> 6;
    float nq = fmaxf(sqrtf(g_sq[b * 128 + r]), 1e-12f);
    float nk = fmaxf(sqrtf(g_sq[512 + b * 128 + (n << 6) + d]), 1e-12f);
    float val = g_S[row * 64 + d] / (nq * nk) * scale[n];
    outAttn[row * 64 + d] = val;
    __shared__ float sm[64];
    sm[d] = val; __syncthreads();
    for (int st = 32; st > 0; st >>= 1){ if (d < st) sm[d] = fmaxf(sm[d], sm[d + st]); __syncthreads(); }
    float mx = sm[0]; __syncthreads();
    float e = expf(val - mx);
    sm[d] = e; __syncthreads();
    for (int st = 32; st > 0; st >>= 1){ if (d < st) sm[d] += sm[d + st]; __syncthreads(); }
    g_A[row * 64 + d] = e / sm[0];
}

// ---------------- out = a @ v : tile 64c x 64px, K=64 ----------------
__global__ void applyav_kernel(const float* __restrict__ V, float* __restrict__ Out){
    __shared__ __align__(16) float sA[8][64];
    __shared__ __align__(16) float sV[8][64];
    int bn = blockIdx.y;
    int b = bn >> 1, n = bn & 1;
    const float* Vb = V + b * CHW + n * HD * HW;
    const float* Ab = g_A + bn * 4096;
    int px0 = blockIdx.x * 64;
    int t = threadIdx.x;
    int c0 = (t >> 4) * 8, pl = (t & 15) * 4;
    int lc = t >> 1,      ld = (t & 1) * 4;
    int vk = t >> 4,      vp = (t & 15) * 4;
    float acc[8][4] = {};
    for (int dd = 0; dd < 64; dd += 8){
        float4 a4 = *(const float4*)(Ab + lc * 64 + dd + ld);
        float4 v4 = *(const float4*)(Vb + (dd + vk) * HW + px0 + vp);
        __syncthreads();
        sA[ld+0][lc]=a4.x; sA[ld+1][lc]=a4.y; sA[ld+2][lc]=a4.z; sA[ld+3][lc]=a4.w;
        *(float4*)&sV[vk][vp] = v4;
        __syncthreads();
        #pragma unroll
        for (int pp = 0; pp < 8; pp++){
            float4 a0 = *(const float4*)&sA[pp][c0];
            float4 a1 = *(const float4*)&sA[pp][c0 + 4];
            float4 vr = *(const float4*)&sV[pp][pl];
            float ar[8] = {a0.x,a0.y,a0.z,a0.w,a1.x,a1.y,a1.z,a1.w};
            float vv[4] = {vr.x,vr.y,vr.z,vr.w};
            #pragma unroll
            for (int i = 0; i < 8; i++)
                #pragma unroll
                for (int j = 0; j < 4; j++)
                    acc[i][j] = fmaf(ar[i], vv[j], acc[i][j]);
        }
    }
    float* Ob = Out + b * CHW + n * HD * HW + px0;
    #pragma unroll
    for (int i = 0; i < 8; i++){
        float4 o; o.x = acc[i][0]; o.y = acc[i][1]; o.z = acc[i][2]; o.w = acc[i][3];
        *(float4*)&Ob[(c0 + i) * HW + pl] = o;
    }
}

// ---------------- channel gate MLP -> sigmoid -> spec_score ----------------
__global__ void gate_kernel(const float* __restrict__ w1, const float* __restrict__ b1,
                            const float* __restrict__ w2, const float* __restrict__ b2,
                            float* __restrict__ out){
    int b = blockIdx.x;
    int c = threadIdx.x;
    __shared__ float avg[128], mx[128], ha[8], hm[8];
    avg[c] = g_avg[b * 128 + c] * (1.0f / HW);
    mx[c]  = g_max[b * 128 + c];
    __syncthreads();
    if (c < 8){
        float sa = b1[c], sm_ = b1[c];
        for (int j = 0; j < 128; j++){
            sa  += w1[c * 128 + j] * avg[j];
            sm_ += w1[c * 128 + j] * mx[j];
        }
        ha[c] = fmaxf(sa, 0.f);
        hm[c] = fmaxf(sm_, 0.f);
    }
    __syncthreads();
    float z = 2.0f * b2[c];
    for (int j = 0; j < 8; j++) z += (ha[j] + hm[j]) * w2[c * 8 + j];
    out[b * 128 + c] = 1.0f / (1.0f + expf(-z));
}

// ---------------- launch ----------------
extern "C" void kernel_launch(void* const* d_in, const int* in_sizes, int n_in,
                              void* d_out, int out_size){
    const float* x        = (const float*)d_in[0];
    const float* ln_in_w  = (const float*)d_in[1];
    const float* ln_in_b  = (const float*)d_in[2];
    const float* wq_pw    = (const float*)d_in[3];
    const float* wq_dw    = (const float*)d_in[4];
    const float* wk_pw    = (const float*)d_in[5];
    const float* wk_dw    = (const float*)d_in[6];
    const float* wv_pw    = (const float*)d_in[7];
    const float* wv_dw    = (const float*)d_in[8];
    const float* scale    = (const float*)d_in[9];
    const float* ln_out_w = (const float*)d_in[10];
    const float* ln_out_b = (const float*)d_in[11];
    const float* f1_pw    = (const float*)d_in[12];
    const float* f1_dw    = (const float*)d_in[13];
    const float* f2_pw    = (const float*)d_in[14];
    const float* f2_dw    = (const float*)d_in[15];
    const float* f_out    = (const float*)d_in[16];
    const float* gw1      = (const float*)d_in[17];
    const float* gb1      = (const float*)d_in[18];
    const float* gw2      = (const float*)d_in[19];
    const float* gb2      = (const float*)d_in[20];
    float* out = (float*)d_out;

    cudaFuncSetAttribute(pwmulti_kernel,  cudaFuncAttributeMaxDynamicSharedMemorySize, SMEM_PW);
    cudaFuncSetAttribute(foutpool_kernel, cudaFuncAttributeMaxDynamicSharedMemorySize, SMEM_FP);

    void *p;
    float *B0,*B1,*B2,*B3,*B4,*B5,*SQ;
    cudaGetSymbolAddress(&p, g_B0);  B0  = (float*)p;
    cudaGetSymbolAddress(&p, g_B1);  B1  = (float*)p;
    cudaGetSymbolAddress(&p, g_B2);  B2  = (float*)p;
    cudaGetSymbolAddress(&p, g_B3);  B3  = (float*)p;
    cudaGetSymbolAddress(&p, g_B4);  B4  = (float*)p;
    cudaGetSymbolAddress(&p, g_B5);  B5  = (float*)p;
    cudaGetSymbolAddress(&p, g_sq);  SQ  = (float*)p;

    dim3 gpx(288, Bn);
    const int dwBlocks = 4608;   // 512 planes * 2304 threads / 256

    init_kernel<<<128, 256>>>();

    // -- attention half --
    lnstats_kernel<<<576, 256>>>(x);
    pwmulti_kernel<<<gpx, 256, SMEM_PW>>>(x, ln_in_w, ln_in_b,
                                          wq_pw, wk_pw, wv_pw,
                                          B0, B1, B5, 3, 0);
    dw3_kernel<<<dwBlocks, 256>>>(B0, wq_dw, B2, SQ);
    dw3_kernel<<<dwBlocks, 256>>>(B1, wk_dw, B3, SQ + 512);
    dw3_kernel<<<dwBlocks, 256>>>(B5, wv_dw, B4, nullptr);

    gram_kernel<<<dim3(KSPLIT, 8), 128>>>(B2, B3);
    attnfin_kernel<<<512, 64>>>(scale, out + 512);
    applyav_kernel<<<dim3(576, 8), 128>>>(B4, B0);

    // -- FFN half --
    lnstats_kernel<<<576, 256>>>(B0);
    pwmulti_kernel<<<gpx, 256, SMEM_PW>>>(B0, ln_out_w, ln_out_b,
                                          f1_pw, f2_pw, nullptr,
                                          B1, B5, nullptr, 2, 1);
    dw3_kernel<<<dwBlocks, 256>>>(B1, f1_dw, B2, nullptr);
    dw3_kernel<<<dwBlocks, 256>>>(B5, f2_dw, B3, nullptr);

    foutpool_kernel<<<gpx, 256, SMEM_FP>>>(B2, B3, f_out);
    gate_kernel<<<4, 128>>>(gw1, gb1, gw2, gb2, out);
}

// round 7
// speedup vs baseline: 2.1764x; 1.1682x over previous
#include <cuda_runtime.h>
#include <cuda_bf16.h>
#include <math.h>

#define Bn 4
#define Cn 128
#define Hn 192
#define Wn 192
#define HW 36864
#define CHW 4718592
#define TOT 18874368
#define NH 2
#define HD 64
#define KSPLIT 144
#define CHUNK 256   // HW / KSPLIT

// smem strides (words) — R4-proven layout
#define WS2 68
#define XS2 136
#define WPLW (128 * WS2)   // 8704
#define XPL  (64 * XS2)    // 8704
#define SMEM_PW ((2 * WPLW + 2 * XPL) * 4)   // 139264 B
#define SMEM_FP (SMEM_PW + 1024)

// ---------------- scratch ----------------
__device__ float g_B0[TOT];
__device__ float g_B1[TOT];
__device__ float g_B2[TOT];
__device__ float g_B3[TOT];
__device__ float g_B4[TOT];
__device__ float g_B5[TOT];
__device__ float g_mu[Bn * HW];
__device__ float g_rs[Bn * HW];
__device__ float g_sq[1024];
__device__ float g_S[32768];
__device__ float g_A[32768];
__device__ float g_avg[512];
__device__ float g_max[512];
__device__ __align__(16) unsigned g_Wpk[7 * 2 * 8192];  // 7 sets x {hi,lo} x 128rows x 64 words

__device__ __forceinline__ float gelu_f(float x){
    return 0.5f * x * (1.0f + erff(x * 0.7071067811865476f));
}
__device__ __forceinline__ void atomicMaxF(float* addr, float v){
    if (v >= 0.0f) atomicMax((int*)addr, __float_as_int(v));
    else           atomicMin((unsigned int*)addr, __float_as_uint(v));
}

// ---------------- bf16 split helpers ----------------
__device__ __forceinline__ unsigned packbf2(float up, float lo){
    unsigned r;
    asm("cvt.rn.bf16x2.f32 %0, %1, %2;" : "=r"(r) : "f"(up), "f"(lo));
    return r;
}
__device__ __forceinline__ void split2(float x, float& hi, float& lo){
    hi = __bfloat162float(__float2bfloat16_rn(x));
    lo = x - hi;
}
__device__ __forceinline__ void packpair(float xlo, float xup, unsigned& wh, unsigned& wl){
    float h0, l0, h1, l1;
    split2(xlo, h0, l0);
    split2(xup, h1, l1);
    wh = packbf2(h1, h0);
    wl = packbf2(l1, l0);
}
__device__ __forceinline__ void mma_bf16(float* c, const unsigned* a, const unsigned* b){
    asm volatile("mma.sync.aligned.m16n8k16.row.col.f32.bf16.bf16.f32 "
        "{%0,%1,%2,%3}, {%4,%5,%6,%7}, {%8,%9}, {%0,%1,%2,%3};"
        : "+f"(c[0]), "+f"(c[1]), "+f"(c[2]), "+f"(c[3])
        : "r"(a[0]), "r"(a[1]), "r"(a[2]), "r"(a[3]), "r"(b[0]), "r"(b[1]));
}

__global__ void nop_kernel(){}

__global__ void init_kernel(){
    int i = blockIdx.x * 256 + threadIdx.x;
    if (i < 32768) g_S[i] = 0.0f;
    if (i < 1024) g_sq[i] = 0.0f;
    if (i < 512){ g_avg[i] = 0.0f; g_max[i] = __int_as_float(0xff800000); }
}

__global__ void zero_mu_kernel(){
    int i = blockIdx.x * 256 + threadIdx.x;   // 147456 threads
    g_mu[i] = 0.0f;
    g_rs[i] = 0.0f;
}

// ---------------- weight prepack: split bf16 hi/lo (full 128-ci rows) ----------------
__global__ void packw_kernel(const float* __restrict__ wq, const float* __restrict__ wk,
                             const float* __restrict__ wv, const float* __restrict__ f1,
                             const float* __restrict__ f2, const float* __restrict__ fo){
    int y = blockIdx.y;
    const float* src; int stride, off;
    switch (y){
        case 0: src = wq; stride = 128; off = 0;   break;
        case 1: src = wk; stride = 128; off = 0;   break;
        case 2: src = wv; stride = 128; off = 0;   break;
        case 3: src = f1; stride = 128; off = 0;   break;
        case 4: src = f2; stride = 128; off = 0;   break;
        case 5: src = fo; stride = 256; off = 0;   break;
        default: src = fo; stride = 256; off = 128; break;
    }
    int idx = blockIdx.x * 256 + threadIdx.x;   // 4096 items: 128 rows x 32 quads
    int row = idx >> 5, quad = idx & 31;
    float4 v = *(const float4*)(src + row * stride + off + quad * 4);
    unsigned h0, l0, h1, l1;
    packpair(v.x, v.y, h0, l0);
    packpair(v.z, v.w, h1, l1);
    unsigned* dh = g_Wpk + y * 16384;
    unsigned* dl = dh + 8192;
    dh[row * 64 + quad * 2]     = h0;  dl[row * 64 + quad * 2]     = l0;
    dh[row * 64 + quad * 2 + 1] = h1;  dl[row * 64 + quad * 2 + 1] = l1;
}

// ---------------- LN stats per pixel (phase 1 only) ----------------
__global__ void lnstats_kernel(const float* __restrict__ X){
    int pix = blockIdx.x * 256 + threadIdx.x;
    int b = pix / HW, p = pix - b * HW;
    const float* xb = X + b * CHW + p;
    float s = 0.f, s2 = 0.f;
    #pragma unroll 8
    for (int c = 0; c < Cn; c++){ float v = xb[c * HW]; s += v; s2 += v * v; }
    float mean = s * (1.0f / Cn);
    float var  = s2 * (1.0f / Cn) - mean * mean;
    g_mu[pix] = mean;
    g_rs[pix] = rsqrtf(var + 1e-5f);
}

// ---- fused multi-set 1x1 conv (bf16 3-term mma), LN on load, prepacked W ----
__global__ void __launch_bounds__(256) pwmulti_kernel(
    const float* __restrict__ X,
    const float* __restrict__ lnw, const float* __restrict__ lnb,
    int s0, int s1, int s2,
    float* __restrict__ Y0, float* __restrict__ Y1, float* __restrict__ Y2,
    int nsets, int doGelu, int statsRaw)
{
    extern __shared__ unsigned smu[];
    unsigned* WPh = smu;
    unsigned* WPl = smu + WPLW;
    unsigned* XPh = smu + 2 * WPLW;
    unsigned* XPl = smu + 2 * WPLW + XPL;
    int b = blockIdx.y, px0 = blockIdx.x * 128;
    int tid = threadIdx.x, lane = tid & 31, wid = tid >> 5;
    int grp = lane >> 2, tig = lane & 3;
    int mtile = (wid >> 2) * 64, ntile = (wid & 3) * 32;

    // ---- X tile load: LN + bf16 hi/lo split, packed by channel pairs ----
    #pragma unroll
    for (int i = 0; i < 8; i++){
        int idx = tid + i * 256;
        int r = idx >> 5, g = idx & 31;
        int px = g * 4;
        float4 mu4 = *(const float4*)(g_mu + b * HW + px0 + px);
        float4 rs4 = *(const float4*)(g_rs + b * HW + px0 + px);
        if (statsRaw){
            mu4.x *= (1.0f / Cn); mu4.y *= (1.0f / Cn);
            mu4.z *= (1.0f / Cn); mu4.w *= (1.0f / Cn);
            rs4.x = rsqrtf(rs4.x * (1.0f / Cn) - mu4.x * mu4.x + 1e-5f);
            rs4.y = rsqrtf(rs4.y * (1.0f / Cn) - mu4.y * mu4.y + 1e-5f);
            rs4.z = rsqrtf(rs4.z * (1.0f / Cn) - mu4.z * mu4.z + 1e-5f);
            rs4.w = rsqrtf(rs4.w * (1.0f / Cn) - mu4.w * mu4.w + 1e-5f);
        }
        float4 x0 = *(const float4*)(X + b * CHW + (2 * r) * HW + px0 + px);
        float4 x1 = *(const float4*)(X + b * CHW + (2 * r + 1) * HW + px0 + px);
        float w0 = lnw[2 * r], b0 = lnb[2 * r];
        float w1 = lnw[2 * r + 1], b1 = lnb[2 * r + 1];
        float a0 = (x0.x - mu4.x) * rs4.x * w0 + b0;
        float a1 = (x0.y - mu4.y) * rs4.y * w0 + b0;
        float a2 = (x0.z - mu4.z) * rs4.z * w0 + b0;
        float a3 = (x0.w - mu4.w) * rs4.w * w0 + b0;
        float c0 = (x1.x - mu4.x) * rs4.x * w1 + b1;
        float c1 = (x1.y - mu4.y) * rs4.y * w1 + b1;
        float c2 = (x1.z - mu4.z) * rs4.z * w1 + b1;
        float c3 = (x1.w - mu4.w) * rs4.w * w1 + b1;
        uint4 vh, vl;
        packpair(a0, c0, vh.x, vl.x);
        packpair(a1, c1, vh.y, vl.y);
        packpair(a2, c2, vh.z, vl.z);
        packpair(a3, c3, vh.w, vl.w);
        *(uint4*)&XPh[r * XS2 + px] = vh;
        *(uint4*)&XPl[r * XS2 + px] = vl;
    }

    int sets[3] = {s0, s1, s2};
    float* Yp[3] = {Y0, Y1, Y2};

    for (int s = 0; s < nsets; s++){
        const unsigned* gw = g_Wpk + sets[s] * 16384;
        __syncthreads();
        #pragma unroll
        for (int i = 0; i < 16; i++){
            int idx = tid + i * 256;          // 4096 uint4: 2 planes x 128 rows x 16
            int plane = idx >> 11;
            int rem = idx & 2047;
            int row = rem >> 4, q = rem & 15;
            uint4 w4 = *(const uint4*)(gw + plane * 8192 + row * 64 + q * 4);
            unsigned* d = plane ? WPl : WPh;
            *(uint4*)&d[row * WS2 + q * 4] = w4;
        }
        __syncthreads();

        float acc[4][4][4] = {};
        #pragma unroll
        for (int ks = 0; ks < 8; ks++){
            int kp = ks * 8 + tig;
            unsigned ah[4][4], al[4][4];
            #pragma unroll
            for (int ma = 0; ma < 4; ma++){
                int r0 = (mtile + ma * 16 + grp) * WS2;
                int r1 = r0 + 8 * WS2;
                ah[ma][0] = WPh[r0 + kp];     ah[ma][1] = WPh[r1 + kp];
                ah[ma][2] = WPh[r0 + kp + 4]; ah[ma][3] = WPh[r1 + kp + 4];
                al[ma][0] = WPl[r0 + kp];     al[ma][1] = WPl[r1 + kp];
                al[ma][2] = WPl[r0 + kp + 4]; al[ma][3] = WPl[r1 + kp + 4];
            }
            #pragma unroll
            for (int na = 0; na < 4; na++){
                int col = ntile + na * 8 + grp;
                unsigned bh[2], bl[2];
                bh[0] = XPh[kp * XS2 + col]; bh[1] = XPh[(kp + 4) * XS2 + col];
                bl[0] = XPl[kp * XS2 + col]; bl[1] = XPl[(kp + 4) * XS2 + col];
                #pragma unroll
                for (int ma = 0; ma < 4; ma++){
                    mma_bf16(acc[ma][na], ah[ma], bh);
                    mma_bf16(acc[ma][na], ah[ma], bl);
                    mma_bf16(acc[ma][na], al[ma], bh);
                }
            }
        }

        float* Yb = Yp[s] + b * CHW + px0;
        #pragma unroll
        for (int ma = 0; ma < 4; ma++){
            #pragma unroll
            for (int na = 0; na < 4; na++){
                int co = mtile + ma * 16 + grp;
                int px = ntile + na * 8 + tig * 2;
                float2 v0 = make_float2(acc[ma][na][0], acc[ma][na][1]);
                float2 v1 = make_float2(acc[ma][na][2], acc[ma][na][3]);
                if (doGelu){
                    v0.x = gelu_f(v0.x); v0.y = gelu_f(v0.y);
                    v1.x = gelu_f(v1.x); v1.y = gelu_f(v1.y);
                }
                *(float2*)&Yb[co * HW + px]       = v0;
                *(float2*)&Yb[(co + 8) * HW + px] = v1;
            }
        }
    }
}

// ---- fused f_out conv (K=256) + gelu(load) + avg/max pooling, prepacked W ----
__global__ void __launch_bounds__(256) foutpool_kernel(
    const float* __restrict__ O1, const float* __restrict__ O2)
{
    extern __shared__ unsigned smu[];
    unsigned* WPh = smu;
    unsigned* WPl = smu + WPLW;
    unsigned* XPh = smu + 2 * WPLW;
    unsigned* XPl = smu + 2 * WPLW + XPL;
    float* ssum = (float*)(smu + 2 * WPLW + 2 * XPL);
    float* smax = ssum + 128;
    int b = blockIdx.y, px0 = blockIdx.x * 128;
    int tid = threadIdx.x, lane = tid & 31, wid = tid >> 5;
    int grp = lane >> 2, tig = lane & 3;
    int mtile = (wid >> 2) * 64, ntile = (wid & 3) * 32;

    if (tid < 128){ ssum[tid] = 0.f; smax[tid] = __int_as_float(0xff800000); }

    float acc[4][4][4] = {};
    for (int ph = 0; ph < 2; ph++){
        const float* src = (ph == 0) ? O1 : O2;
        const unsigned* gw = g_Wpk + (5 + ph) * 16384;
        __syncthreads();
        #pragma unroll
        for (int i = 0; i < 8; i++){
            int idx = tid + i * 256;
            int r = idx >> 5, g = idx & 31;
            int px = g * 4;
            float4 x0 = *(const float4*)(src + b * CHW + (2 * r) * HW + px0 + px);
            float4 x1 = *(const float4*)(src + b * CHW + (2 * r + 1) * HW + px0 + px);
            x0.x = gelu_f(x0.x); x0.y = gelu_f(x0.y); x0.z = gelu_f(x0.z); x0.w = gelu_f(x0.w);
            x1.x = gelu_f(x1.x); x1.y = gelu_f(x1.y); x1.z = gelu_f(x1.z); x1.w = gelu_f(x1.w);
            uint4 vh, vl;
            packpair(x0.x, x1.x, vh.x, vl.x);
            packpair(x0.y, x1.y, vh.y, vl.y);
            packpair(x0.z, x1.z, vh.z, vl.z);
            packpair(x0.w, x1.w, vh.w, vl.w);
            *(uint4*)&XPh[r * XS2 + px] = vh;
            *(uint4*)&XPl[r * XS2 + px] = vl;
        }
        #pragma unroll
        for (int i = 0; i < 16; i++){
            int idx = tid + i * 256;
            int plane = idx >> 11;
            int rem = idx & 2047;
            int row = rem >> 4, q = rem & 15;
            uint4 w4 = *(const uint4*)(gw + plane * 8192 + row * 64 + q * 4);
            unsigned* d = plane ? WPl : WPh;
            *(uint4*)&d[row * WS2 + q * 4] = w4;
        }
        __syncthreads();

        #pragma unroll
        for (int ks = 0; ks < 8; ks++){
            int kp = ks * 8 + tig;
            unsigned ah[4][4], al[4][4];
            #pragma unroll
            for (int ma = 0; ma < 4; ma++){
                int r0 = (mtile + ma * 16 + grp) * WS2;
                int r1 = r0 + 8 * WS2;
                ah[ma][0] = WPh[r0 + kp];     ah[ma][1] = WPh[r1 + kp];
                ah[ma][2] = WPh[r0 + kp + 4]; ah[ma][3] = WPh[r1 + kp + 4];
                al[ma][0] = WPl[r0 + kp];     al[ma][1] = WPl[r1 + kp];
                al[ma][2] = WPl[r0 + kp + 4]; al[ma][3] = WPl[r1 + kp + 4];
            }
            #pragma unroll
            for (int na = 0; na < 4; na++){
                int col = ntile + na * 8 + grp;
                unsigned bh[2], bl[2];
                bh[0] = XPh[kp * XS2 + col]; bh[1] = XPh[(kp + 4) * XS2 + col];
                bl[0] = XPl[kp * XS2 + col]; bl[1] = XPl[(kp + 4) * XS2 + col];
                #pragma unroll
                for (int ma = 0; ma < 4; ma++){
                    mma_bf16(acc[ma][na], ah[ma], bh);
                    mma_bf16(acc[ma][na], ah[ma], bl);
                    mma_bf16(acc[ma][na], al[ma], bh);
                }
            }
        }
    }
    __syncthreads();

    #pragma unroll
    for (int ma = 0; ma < 4; ma++){
        float s0 = 0.f, s1 = 0.f;
        float m0 = __int_as_float(0xff800000), m1 = m0;
        #pragma unroll
        for (int na = 0; na < 4; na++){
            s0 += acc[ma][na][0] + acc[ma][na][1];
            s1 += acc[ma][na][2] + acc[ma][na][3];
            m0 = fmaxf(m0, fmaxf(acc[ma][na][0], acc[ma][na][1]));
            m1 = fmaxf(m1, fmaxf(acc[ma][na][2], acc[ma][na][3]));
        }
        #pragma unroll
        for (int st = 1; st <= 2; st <<= 1){
            s0 += __shfl_xor_sync(0xffffffffu, s0, st);
            s1 += __shfl_xor_sync(0xffffffffu, s1, st);
            m0 = fmaxf(m0, __shfl_xor_sync(0xffffffffu, m0, st));
            m1 = fmaxf(m1, __shfl_xor_sync(0xffffffffu, m1, st));
        }
        if (tig == 0){
            int co = mtile + ma * 16 + grp;
            atomicAdd(&ssum[co], s0);     atomicMaxF(&smax[co], m0);
            atomicAdd(&ssum[co + 8], s1); atomicMaxF(&smax[co + 8], m1);
        }
    }
    __syncthreads();
    if (tid < 128){
        atomicAdd(&g_avg[b * 128 + tid], ssum[tid]);
        atomicMaxF(&g_max[b * 128 + tid], smax[tid]);
    }
}

// ---------------- depthwise 3x3 pad 1: 8px x 2rows per thread, multi-set ----------------
__global__ void dw3_kernel(
    const float* __restrict__ S0, float* __restrict__ D0, float* __restrict__ Q0, const float* __restrict__ Wd0,
    const float* __restrict__ S1, float* __restrict__ D1, float* __restrict__ Q1, const float* __restrict__ Wd1,
    const float* __restrict__ S2, float* __restrict__ D2, float* __restrict__ Q2, const float* __restrict__ Wd2)
{
    const float* X; float* Y; float* sq; const float* Wd;
    switch (blockIdx.y){
        case 0: X = S0; Y = D0; sq = Q0; Wd = Wd0; break;
        case 1: X = S1; Y = D1; sq = Q1; Wd = Wd1; break;
        default: X = S2; Y = D2; sq = Q2; Wd = Wd2; break;
    }
    int idx = blockIdx.x * 256 + threadIdx.x;
    int plane = idx / 2304;
    int r = idx - plane * 2304;
    int hp = r / 24, wb = r - hp * 24;
    int h = hp * 2, w = wb * 8;
    int c = plane & 127;
    const float* xp = X + plane * HW;
    const float* wdp = Wd + c * 9;
    float wd9[9];
    #pragma unroll
    for (int i = 0; i < 9; i++) wd9[i] = wdp[i];

    float ld[4][10];
    #pragma unroll
    for (int rr = 0; rr < 4; rr++){
        int hh = h - 1 + rr;
        if ((unsigned)hh < Hn){
            const float* rp_ = xp + hh * Wn + w;
            float4 a = *(const float4*)rp_;
            float4 bq = *(const float4*)(rp_ + 4);
            ld[rr][0] = (w > 0) ? rp_[-1] : 0.f;
            ld[rr][1] = a.x; ld[rr][2] = a.y; ld[rr][3] = a.z; ld[rr][4] = a.w;
            ld[rr][5] = bq.x; ld[rr][6] = bq.y; ld[rr][7] = bq.z; ld[rr][8] = bq.w;
            ld[rr][9] = (w + 8 < Wn) ? rp_[8] : 0.f;
        } else {
            #pragma unroll
            for (int j = 0; j < 10; j++) ld[rr][j] = 0.f;
        }
    }
    float o[2][8];
    #pragma unroll
    for (int orow = 0; orow < 2; orow++)
        #pragma unroll
        for (int j = 0; j < 8; j++) o[orow][j] = 0.f;
    #pragma unroll
    for (int orow = 0; orow < 2; orow++){
        #pragma unroll
        for (int t = 0; t < 3; t++){
            float k0 = wd9[t * 3 + 0], k1 = wd9[t * 3 + 1], k2 = wd9[t * 3 + 2];
            #pragma unroll
            for (int j = 0; j < 8; j++)
                o[orow][j] = fmaf(ld[orow + t][j], k0,
                             fmaf(ld[orow + t][j + 1], k1,
                             fmaf(ld[orow + t][j + 2], k2, o[orow][j])));
        }
    }
    #pragma unroll
    for (int orow = 0; orow < 2; orow++){
        float4 v0, v1;
        v0.x = o[orow][0]; v0.y = o[orow][1]; v0.z = o[orow][2]; v0.w = o[orow][3];
        v1.x = o[orow][4]; v1.y = o[orow][5]; v1.z = o[orow][6]; v1.w = o[orow][7];
        *(float4*)&Y[plane * HW + (h + orow) * Wn + w]     = v0;
        *(float4*)&Y[plane * HW + (h + orow) * Wn + w + 4] = v1;
    }
    if (sq){
        float s = 0.f;
        #pragma unroll
        for (int orow = 0; orow < 2; orow++)
            #pragma unroll
            for (int j = 0; j < 8; j++) s += o[orow][j] * o[orow][j];
        #pragma unroll
        for (int st = 16; st > 0; st >>= 1)
            s += __shfl_down_sync(0xffffffffu, s, st);
        if ((threadIdx.x & 31) == 0) atomicAdd(&sq[plane], s);
    }
}

// ---------------- raw gram S += q k^T, split-K over pixels ----------------
__global__ void gram_kernel(const float* __restrict__ Q, const float* __restrict__ K){
    __shared__ __align__(16) float sq[8][64];
    __shared__ __align__(16) float sk[8][64];
    int bn = blockIdx.y;
    int b = bn >> 1, n = bn & 1;
    const float* Qb = Q + b * CHW + n * HD * HW;
    const float* Kb = K + b * CHW + n * HD * HW;
    int p0 = blockIdx.x * CHUNK;
    int t  = threadIdx.x;
    int c0 = (t >> 4) * 8;
    int d0 = (t & 15) * 4;
    int lc = t >> 1;
    int lp = (t & 1) * 4;
    float acc[8][4] = {};
    for (int p = p0; p < p0 + CHUNK; p += 8){
        float4 qa = *(const float4*)(Qb + lc * HW + p + lp);
        float4 ka = *(const float4*)(Kb + lc * HW + p + lp);
        __syncthreads();
        sq[lp+0][lc]=qa.x; sq[lp+1][lc]=qa.y; sq[lp+2][lc]=qa.z; sq[lp+3][lc]=qa.w;
        sk[lp+0][lc]=ka.x; sk[lp+1][lc]=ka.y; sk[lp+2][lc]=ka.z; sk[lp+3][lc]=ka.w;
        __syncthreads();
        #pragma unroll
        for (int pp = 0; pp < 8; pp++){
            float4 w0 = *(const float4*)&sq[pp][c0];
            float4 w1 = *(const float4*)&sq[pp][c0 + 4];
            float4 xr = *(const float4*)&sk[pp][d0];
            float wr[8] = {w0.x,w0.y,w0.z,w0.w,w1.x,w1.y,w1.z,w1.w};
            float xv[4] = {xr.x,xr.y,xr.z,xr.w};
            #pragma unroll
            for (int i = 0; i < 8; i++)
                #pragma unroll
                for (int j = 0; j < 4; j++)
                    acc[i][j] = fmaf(wr[i], xv[j], acc[i][j]);
        }
    }
    float* Sp = g_S + bn * 4096;
    #pragma unroll
    for (int i = 0; i < 8; i++)
        #pragma unroll
        for (int j = 0; j < 4; j++)
            atomicAdd(&Sp[(c0 + i) * 64 + d0 + j], acc[i][j]);
}

// ---------------- finalize attn (write attn_weight) + softmax ----------------
__global__ void attnfin_kernel(const float* __restrict__ scale, float* __restrict__ outAttn){
    int row = blockIdx.x;
    int d   = threadIdx.x;
    int b = row >> 7;
    int r = row & 127;
    int n = r >> 6;
    float nq = fmaxf(sqrtf(g_sq[b * 128 + r]), 1e-12f);
    float nk = fmaxf(sqrtf(g_sq[512 + b * 128 + (n << 6) + d]), 1e-12f);
    float val = g_S[row * 64 + d] / (nq * nk) * scale[n];
    outAttn[row * 64 + d] = val;
    __shared__ float sm[64];
    sm[d] = val; __syncthreads();
    for (int st = 32; st > 0; st >>= 1){ if (d < st) sm[d] = fmaxf(sm[d], sm[d + st]); __syncthreads(); }
    float mx = sm[0]; __syncthreads();
    float e = expf(val - mx);
    sm[d] = e; __syncthreads();
    for (int st = 32; st > 0; st >>= 1){ if (d < st) sm[d] += sm[d + st]; __syncthreads(); }
    g_A[row * 64 + d] = e / sm[0];
}

// ---------------- out = a @ v, with fused LN-stats accumulation ----------------
__global__ void applyav_kernel(const float* __restrict__ V, float* __restrict__ Out){
    __shared__ __align__(16) float sA[8][64];
    __shared__ __align__(16) float sV[8][64];
    __shared__ float px_s[64], px_s2[64];
    int bn = blockIdx.y;
    int b = bn >> 1, n = bn & 1;
    const float* Vb = V + b * CHW + n * HD * HW;
    const float* Ab = g_A + bn * 4096;
    int px0 = blockIdx.x * 64;
    int t = threadIdx.x;
    int c0 = (t >> 4) * 8, pl = (t & 15) * 4;
    int lc = t >> 1,      ld = (t & 1) * 4;
    int vk = t >> 4,      vp = (t & 15) * 4;
    if (t < 64){ px_s[t] = 0.f; px_s2[t] = 0.f; }
    float acc[8][4] = {};
    for (int dd = 0; dd < 64; dd += 8){
        float4 a4 = *(const float4*)(Ab + lc * 64 + dd + ld);
        float4 v4 = *(const float4*)(Vb + (dd + vk) * HW + px0 + vp);
        __syncthreads();
        sA[ld+0][lc]=a4.x; sA[ld+1][lc]=a4.y; sA[ld+2][lc]=a4.z; sA[ld+3][lc]=a4.w;
        *(float4*)&sV[vk][vp] = v4;
        __syncthreads();
        #pragma unroll
        for (int pp = 0; pp < 8; pp++){
            float4 a0 = *(const float4*)&sA[pp][c0];
            float4 a1 = *(const float4*)&sA[pp][c0 + 4];
            float4 vr = *(const float4*)&sV[pp][pl];
            float ar[8] = {a0.x,a0.y,a0.z,a0.w,a1.x,a1.y,a1.z,a1.w};
            float vv[4] = {vr.x,vr.y,vr.z,vr.w};
            #pragma unroll
            for (int i = 0; i < 8; i++)
                #pragma unroll
                for (int j = 0; j < 4; j++)
                    acc[i][j] = fmaf(ar[i], vv[j], acc[i][j]);
        }
    }
    float* Ob = Out + b * CHW + n * HD * HW + px0;
    #pragma unroll
    for (int i = 0; i < 8; i++){
        float4 o; o.x = acc[i][0]; o.y = acc[i][1]; o.z = acc[i][2]; o.w = acc[i][3];
        *(float4*)&Ob[(c0 + i) * HW + pl] = o;
    }
    // LN-stats partial sums over this block's 64 channels
    #pragma unroll
    for (int j = 0; j < 4; j++){
        float s = 0.f, s2 = 0.f;
        #pragma unroll
        for (int i = 0; i < 8; i++){ s += acc[i][j]; s2 += acc[i][j] * acc[i][j]; }
        atomicAdd(&px_s[pl + j], s);
        atomicAdd(&px_s2[pl + j], s2);
    }
    __syncthreads();
    if (t < 64){
        int gp = b * HW + px0 + t;
        atomicAdd(&g_mu[gp], px_s[t]);
        atomicAdd(&g_rs[gp], px_s2[t]);
    }
}

// ---------------- channel gate MLP -> sigmoid -> spec_score ----------------
__global__ void gate_kernel(const float* __restrict__ w1, const float* __restrict__ b1,
                            const float* __restrict__ w2, const float* __restrict__ b2,
                            float* __restrict__ out){
    int b = blockIdx.x;
    int c = threadIdx.x;
    __shared__ float avg[128], mx[128], ha[8], hm[8];
    avg[c] = g_avg[b * 128 + c] * (1.0f / HW);
    mx[c]  = g_max[b * 128 + c];
    __syncthreads();
    if (c < 8){
        float sa = b1[c], sm_ = b1[c];
        for (int j = 0; j < 128; j++){
            sa  += w1[c * 128 + j] * avg[j];
            sm_ += w1[c * 128 + j] * mx[j];
        }
        ha[c] = fmaxf(sa, 0.f);
        hm[c] = fmaxf(sm_, 0.f);
    }
    __syncthreads();
    float z = 2.0f * b2[c];
    for (int j = 0; j < 8; j++) z += (ha[j] + hm[j]) * w2[c * 8 + j];
    out[b * 128 + c] = 1.0f / (1.0f + expf(-z));
}

// ---------------- launch ----------------
extern "C" void kernel_launch(void* const* d_in, const int* in_sizes, int n_in,
                              void* d_out, int out_size){
    const float* x        = (const float*)d_in[0];
    const float* ln_in_w  = (const float*)d_in[1];
    const float* ln_in_b  = (const float*)d_in[2];
    const float* wq_pw    = (const float*)d_in[3];
    const float* wq_dw    = (const float*)d_in[4];
    const float* wk_pw    = (const float*)d_in[5];
    const float* wk_dw    = (const float*)d_in[6];
    const float* wv_pw    = (const float*)d_in[7];
    const float* wv_dw    = (const float*)d_in[8];
    const float* scale    = (const float*)d_in[9];
    const float* ln_out_w = (const float*)d_in[10];
    const float* ln_out_b = (const float*)d_in[11];
    const float* f1_pw    = (const float*)d_in[12];
    const float* f1_dw    = (const float*)d_in[13];
    const float* f2_pw    = (const float*)d_in[14];
    const float* f2_dw    = (const float*)d_in[15];
    const float* f_out    = (const float*)d_in[16];
    const float* gw1      = (const float*)d_in[17];
    const float* gb1      = (const float*)d_in[18];
    const float* gw2      = (const float*)d_in[19];
    const float* gb2      = (const float*)d_in[20];
    float* out = (float*)d_out;

    cudaFuncSetAttribute(pwmulti_kernel,  cudaFuncAttributeMaxDynamicSharedMemorySize, SMEM_PW);
    cudaFuncSetAttribute(foutpool_kernel, cudaFuncAttributeMaxDynamicSharedMemorySize, SMEM_FP);

    void *p;
    float *B0,*B1,*B2,*B3,*B4,*B5,*SQ;
    cudaGetSymbolAddress(&p, g_B0);  B0  = (float*)p;
    cudaGetSymbolAddress(&p, g_B1);  B1  = (float*)p;
    cudaGetSymbolAddress(&p, g_B2);  B2  = (float*)p;
    cudaGetSymbolAddress(&p, g_B3);  B3  = (float*)p;
    cudaGetSymbolAddress(&p, g_B4);  B4  = (float*)p;
    cudaGetSymbolAddress(&p, g_B5);  B5  = (float*)p;
    cudaGetSymbolAddress(&p, g_sq);  SQ  = (float*)p;

    dim3 gpx(288, Bn);

    // launch order crafted so ncu (-s 5 -c 1) profiles pwmulti#1 (6th launch)
    init_kernel<<<128, 256>>>();
    packw_kernel<<<dim3(16, 7), 256>>>(wq_pw, wk_pw, wv_pw, f1_pw, f2_pw, f_out);
    lnstats_kernel<<<576, 256>>>(x);
    nop_kernel<<<1, 1>>>();
    nop_kernel<<<1, 1>>>();

    pwmulti_kernel<<<gpx, 256, SMEM_PW>>>(x, ln_in_w, ln_in_b,
                                          0, 1, 2, B0, B1, B5, 3, 0, 0);
    dw3_kernel<<<dim3(4608, 3), 256>>>(B0, B2, SQ,       wq_dw,
                                       B1, B3, SQ + 512, wk_dw,
                                       B5, B4, nullptr,  wv_dw);
    gram_kernel<<<dim3(KSPLIT, 8), 128>>>(B2, B3);
    zero_mu_kernel<<<576, 256>>>();
    attnfin_kernel<<<512, 64>>>(scale, out + 512);
    applyav_kernel<<<dim3(576, 8), 128>>>(B4, B0);

    pwmulti_kernel<<<gpx, 256, SMEM_PW>>>(B0, ln_out_w, ln_out_b,
                                          3, 4, 4, B1, B5, nullptr, 2, 1, 1);
    dw3_kernel<<<dim3(4608, 2), 256>>>(B1, B2, nullptr, f1_dw,
                                       B5, B3, nullptr, f2_dw,
                                       nullptr, nullptr, nullptr, nullptr);
    foutpool_kernel<<<gpx, 256, SMEM_FP>>>(B2, B3);
    gate_kernel<<<4, 128>>>(gw1, gb1, gw2, gb2, out);
}

// round 8
// speedup vs baseline: 2.2101x; 1.0155x over previous
#include <cuda_runtime.h>
#include <cuda_bf16.h>
#include <math.h>

#define Bn 4
#define Cn 128
#define Hn 192
#define Wn 192
#define HW 36864
#define CHW 4718592
#define TOT 18874368
#define NH 2
#define HD 64

// pw smem strides (words) — proven layout
#define WS2 68
#define XS2 136
#define WPLW (128 * WS2)   // 8704
#define XPL  (64 * XS2)    // 8704
#define SMEM_PW ((2 * WPLW + 2 * XPL) * 4)   // 139264 B
#define SMEM_FP (SMEM_PW + 1024)

// gram smem
#define GQS 68
#define GKS 136
#define GQPL (64 * GQS)    // 4352
#define GKPL (64 * GKS)    // 8704
#define SMEM_G ((2 * GQPL + 2 * GKPL) * 4)   // 104448 B
#define GSPLIT 72          // x4 inner chunks of 128 px

// applyav smem
#define AAS 36
#define AVS 136
#define AAPL (64 * AAS)    // 2304
#define AVPL (32 * AVS)    // 4352
#define SMEM_AV ((2 * AAPL + 2 * AVPL) * 4 + 1024)

// ---------------- scratch ----------------
__device__ float g_B0[TOT];
__device__ float g_B1[TOT];
__device__ float g_B2[TOT];
__device__ float g_B3[TOT];
__device__ float g_B4[TOT];
__device__ float g_B5[TOT];
__device__ float g_mu[Bn * HW];
__device__ float g_rs[Bn * HW];
__device__ float g_sq[1024];
__device__ float g_S[32768];
__device__ __align__(16) unsigned g_Apk[8 * 2 * AAPL];  // packed softmax per (b,n)
__device__ float g_avg[512];
__device__ float g_max[512];
__device__ __align__(16) unsigned g_Wpk[7 * 2 * 8192];

__device__ __forceinline__ float gelu_f(float x){
    return 0.5f * x * (1.0f + erff(x * 0.7071067811865476f));
}
__device__ __forceinline__ void atomicMaxF(float* addr, float v){
    if (v >= 0.0f) atomicMax((int*)addr, __float_as_int(v));
    else           atomicMin((unsigned int*)addr, __float_as_uint(v));
}

// ---------------- bf16 split helpers ----------------
__device__ __forceinline__ unsigned packbf2(float up, float lo){
    unsigned r;
    asm("cvt.rn.bf16x2.f32 %0, %1, %2;" : "=r"(r) : "f"(up), "f"(lo));
    return r;
}
__device__ __forceinline__ void split2(float x, float& hi, float& lo){
    hi = __bfloat162float(__float2bfloat16_rn(x));
    lo = x - hi;
}
__device__ __forceinline__ void packpair(float xlo, float xup, unsigned& wh, unsigned& wl){
    float h0, l0, h1, l1;
    split2(xlo, h0, l0);
    split2(xup, h1, l1);
    wh = packbf2(h1, h0);
    wl = packbf2(l1, l0);
}
__device__ __forceinline__ void mma_bf16(float* c, const unsigned* a, const unsigned* b){
    asm volatile("mma.sync.aligned.m16n8k16.row.col.f32.bf16.bf16.f32 "
        "{%0,%1,%2,%3}, {%4,%5,%6,%7}, {%8,%9}, {%0,%1,%2,%3};"
        : "+f"(c[0]), "+f"(c[1]), "+f"(c[2]), "+f"(c[3])
        : "r"(a[0]), "r"(a[1]), "r"(a[2]), "r"(a[3]), "r"(b[0]), "r"(b[1]));
}

__global__ void nop_kernel(){}

__global__ void init_kernel(){
    int i = blockIdx.x * 256 + threadIdx.x;
    if (i < 32768) g_S[i] = 0.0f;
    if (i < 1024) g_sq[i] = 0.0f;
    if (i < 512){ g_avg[i] = 0.0f; g_max[i] = __int_as_float(0xff800000); }
}

__global__ void zero_mu_kernel(){
    int i = blockIdx.x * 256 + threadIdx.x;
    g_mu[i] = 0.0f;
    g_rs[i] = 0.0f;
}

// ---------------- weight prepack ----------------
__global__ void packw_kernel(const float* __restrict__ wq, const float* __restrict__ wk,
                             const float* __restrict__ wv, const float* __restrict__ f1,
                             const float* __restrict__ f2, const float* __restrict__ fo){
    int y = blockIdx.y;
    const float* src; int stride, off;
    switch (y){
        case 0: src = wq; stride = 128; off = 0;   break;
        case 1: src = wk; stride = 128; off = 0;   break;
        case 2: src = wv; stride = 128; off = 0;   break;
        case 3: src = f1; stride = 128; off = 0;   break;
        case 4: src = f2; stride = 128; off = 0;   break;
        case 5: src = fo; stride = 256; off = 0;   break;
        default: src = fo; stride = 256; off = 128; break;
    }
    int idx = blockIdx.x * 256 + threadIdx.x;   // 4096 items: 128 rows x 32 quads
    int row = idx >> 5, quad = idx & 31;
    float4 v = *(const float4*)(src + row * stride + off + quad * 4);
    unsigned h0, l0, h1, l1;
    packpair(v.x, v.y, h0, l0);
    packpair(v.z, v.w, h1, l1);
    unsigned* dh = g_Wpk + y * 16384;
    unsigned* dl = dh + 8192;
    dh[row * 64 + quad * 2]     = h0;  dl[row * 64 + quad * 2]     = l0;
    dh[row * 64 + quad * 2 + 1] = h1;  dl[row * 64 + quad * 2 + 1] = l1;
}

// ---------------- LN stats per pixel (phase 1) ----------------
__global__ void lnstats_kernel(const float* __restrict__ X){
    int pix = blockIdx.x * 256 + threadIdx.x;
    int b = pix / HW, p = pix - b * HW;
    const float* xb = X + b * CHW + p;
    float s = 0.f, s2 = 0.f;
    #pragma unroll 8
    for (int c = 0; c < Cn; c++){ float v = xb[c * HW]; s += v; s2 += v * v; }
    float mean = s * (1.0f / Cn);
    float var  = s2 * (1.0f / Cn) - mean * mean;
    g_mu[pix] = mean;
    g_rs[pix] = rsqrtf(var + 1e-5f);
}

// ---- fused multi-set 1x1 conv (bf16 3-term mma), LN on load, prepacked W ----
__global__ void __launch_bounds__(256) pwmulti_kernel(
    const float* __restrict__ X,
    const float* __restrict__ lnw, const float* __restrict__ lnb,
    int s0, int s1, int s2,
    float* __restrict__ Y0, float* __restrict__ Y1, float* __restrict__ Y2,
    int nsets, int doGelu, int statsRaw)
{
    extern __shared__ unsigned smu[];
    unsigned* WPh = smu;
    unsigned* WPl = smu + WPLW;
    unsigned* XPh = smu + 2 * WPLW;
    unsigned* XPl = smu + 2 * WPLW + XPL;
    int b = blockIdx.y, px0 = blockIdx.x * 128;
    int tid = threadIdx.x, lane = tid & 31, wid = tid >> 5;
    int grp = lane >> 2, tig = lane & 3;
    int mtile = (wid >> 2) * 64, ntile = (wid & 3) * 32;

    #pragma unroll
    for (int i = 0; i < 8; i++){
        int idx = tid + i * 256;
        int r = idx >> 5, g = idx & 31;
        int px = g * 4;
        float4 mu4 = *(const float4*)(g_mu + b * HW + px0 + px);
        float4 rs4 = *(const float4*)(g_rs + b * HW + px0 + px);
        if (statsRaw){
            mu4.x *= (1.0f / Cn); mu4.y *= (1.0f / Cn);
            mu4.z *= (1.0f / Cn); mu4.w *= (1.0f / Cn);
            rs4.x = rsqrtf(rs4.x * (1.0f / Cn) - mu4.x * mu4.x + 1e-5f);
            rs4.y = rsqrtf(rs4.y * (1.0f / Cn) - mu4.y * mu4.y + 1e-5f);
            rs4.z = rsqrtf(rs4.z * (1.0f / Cn) - mu4.z * mu4.z + 1e-5f);
            rs4.w = rsqrtf(rs4.w * (1.0f / Cn) - mu4.w * mu4.w + 1e-5f);
        }
        float4 x0 = *(const float4*)(X + b * CHW + (2 * r) * HW + px0 + px);
        float4 x1 = *(const float4*)(X + b * CHW + (2 * r + 1) * HW + px0 + px);
        float w0 = lnw[2 * r], b0 = lnb[2 * r];
        float w1 = lnw[2 * r + 1], b1 = lnb[2 * r + 1];
        float a0 = (x0.x - mu4.x) * rs4.x * w0 + b0;
        float a1 = (x0.y - mu4.y) * rs4.y * w0 + b0;
        float a2 = (x0.z - mu4.z) * rs4.z * w0 + b0;
        float a3 = (x0.w - mu4.w) * rs4.w * w0 + b0;
        float c0 = (x1.x - mu4.x) * rs4.x * w1 + b1;
        float c1 = (x1.y - mu4.y) * rs4.y * w1 + b1;
        float c2 = (x1.z - mu4.z) * rs4.z * w1 + b1;
        float c3 = (x1.w - mu4.w) * rs4.w * w1 + b1;
        uint4 vh, vl;
        packpair(a0, c0, vh.x, vl.x);
        packpair(a1, c1, vh.y, vl.y);
        packpair(a2, c2, vh.z, vl.z);
        packpair(a3, c3, vh.w, vl.w);
        *(uint4*)&XPh[r * XS2 + px] = vh;
        *(uint4*)&XPl[r * XS2 + px] = vl;
    }

    int sets[3] = {s0, s1, s2};
    float* Yp[3] = {Y0, Y1, Y2};

    for (int s = 0; s < nsets; s++){
        const unsigned* gw = g_Wpk + sets[s] * 16384;
        __syncthreads();
        #pragma unroll
        for (int i = 0; i < 16; i++){
            int idx = tid + i * 256;
            int plane = idx >> 11;
            int rem = idx & 2047;
            int row = rem >> 4, q = rem & 15;
            uint4 w4 = *(const uint4*)(gw + plane * 8192 + row * 64 + q * 4);
            unsigned* d = plane ? WPl : WPh;
            *(uint4*)&d[row * WS2 + q * 4] = w4;
        }
        __syncthreads();

        float acc[4][4][4] = {};
        #pragma unroll
        for (int ks = 0; ks < 8; ks++){
            int kp = ks * 8 + tig;
            unsigned ah[4][4], al[4][4];
            #pragma unroll
            for (int ma = 0; ma < 4; ma++){
                int r0 = (mtile + ma * 16 + grp) * WS2;
                int r1 = r0 + 8 * WS2;
                ah[ma][0] = WPh[r0 + kp];     ah[ma][1] = WPh[r1 + kp];
                ah[ma][2] = WPh[r0 + kp + 4]; ah[ma][3] = WPh[r1 + kp + 4];
                al[ma][0] = WPl[r0 + kp];     al[ma][1] = WPl[r1 + kp];
                al[ma][2] = WPl[r0 + kp + 4]; al[ma][3] = WPl[r1 + kp + 4];
            }
            #pragma unroll
            for (int na = 0; na < 4; na++){
                int col = ntile + na * 8 + grp;
                unsigned bh[2], bl[2];
                bh[0] = XPh[kp * XS2 + col]; bh[1] = XPh[(kp + 4) * XS2 + col];
                bl[0] = XPl[kp * XS2 + col]; bl[1] = XPl[(kp + 4) * XS2 + col];
                #pragma unroll
                for (int ma = 0; ma < 4; ma++){
                    mma_bf16(acc[ma][na], ah[ma], bh);
                    mma_bf16(acc[ma][na], ah[ma], bl);
                    mma_bf16(acc[ma][na], al[ma], bh);
                }
            }
        }

        float* Yb = Yp[s] + b * CHW + px0;
        #pragma unroll
        for (int ma = 0; ma < 4; ma++){
            #pragma unroll
            for (int na = 0; na < 4; na++){
                int co = mtile + ma * 16 + grp;
                int px = ntile + na * 8 + tig * 2;
                float2 v0 = make_float2(acc[ma][na][0], acc[ma][na][1]);
                float2 v1 = make_float2(acc[ma][na][2], acc[ma][na][3]);
                if (doGelu){
                    v0.x = gelu_f(v0.x); v0.y = gelu_f(v0.y);
                    v1.x = gelu_f(v1.x); v1.y = gelu_f(v1.y);
                }
                *(float2*)&Yb[co * HW + px]       = v0;
                *(float2*)&Yb[(co + 8) * HW + px] = v1;
            }
        }
    }
}

// ---- fused f_out conv (K=256) + gelu(load) + avg/max pooling ----
__global__ void __launch_bounds__(256) foutpool_kernel(
    const float* __restrict__ O1, const float* __restrict__ O2)
{
    extern __shared__ unsigned smu[];
    unsigned* WPh = smu;
    unsigned* WPl = smu + WPLW;
    unsigned* XPh = smu + 2 * WPLW;
    unsigned* XPl = smu + 2 * WPLW + XPL;
    float* ssum = (float*)(smu + 2 * WPLW + 2 * XPL);
    float* smax = ssum + 128;
    int b = blockIdx.y, px0 = blockIdx.x * 128;
    int tid = threadIdx.x, lane = tid & 31, wid = tid >> 5;
    int grp = lane >> 2, tig = lane & 3;
    int mtile = (wid >> 2) * 64, ntile = (wid & 3) * 32;

    if (tid < 128){ ssum[tid] = 0.f; smax[tid] = __int_as_float(0xff800000); }

    float acc[4][4][4] = {};
    for (int ph = 0; ph < 2; ph++){
        const float* src = (ph == 0) ? O1 : O2;
        const unsigned* gw = g_Wpk + (5 + ph) * 16384;
        __syncthreads();
        #pragma unroll
        for (int i = 0; i < 8; i++){
            int idx = tid + i * 256;
            int r = idx >> 5, g = idx & 31;
            int px = g * 4;
            float4 x0 = *(const float4*)(src + b * CHW + (2 * r) * HW + px0 + px);
            float4 x1 = *(const float4*)(src + b * CHW + (2 * r + 1) * HW + px0 + px);
            x0.x = gelu_f(x0.x); x0.y = gelu_f(x0.y); x0.z = gelu_f(x0.z); x0.w = gelu_f(x0.w);
            x1.x = gelu_f(x1.x); x1.y = gelu_f(x1.y); x1.z = gelu_f(x1.z); x1.w = gelu_f(x1.w);
            uint4 vh, vl;
            packpair(x0.x, x1.x, vh.x, vl.x);
            packpair(x0.y, x1.y, vh.y, vl.y);
            packpair(x0.z, x1.z, vh.z, vl.z);
            packpair(x0.w, x1.w, vh.w, vl.w);
            *(uint4*)&XPh[r * XS2 + px] = vh;
            *(uint4*)&XPl[r * XS2 + px] = vl;
        }
        #pragma unroll
        for (int i = 0; i < 16; i++){
            int idx = tid + i * 256;
            int plane = idx >> 11;
            int rem = idx & 2047;
            int row = rem >> 4, q = rem & 15;
            uint4 w4 = *(const uint4*)(gw + plane * 8192 + row * 64 + q * 4);
            unsigned* d = plane ? WPl : WPh;
            *(uint4*)&d[row * WS2 + q * 4] = w4;
        }
        __syncthreads();

        #pragma unroll
        for (int ks = 0; ks < 8; ks++){
            int kp = ks * 8 + tig;
            unsigned ah[4][4], al[4][4];
            #pragma unroll
            for (int ma = 0; ma < 4; ma++){
                int r0 = (mtile + ma * 16 + grp) * WS2;
                int r1 = r0 + 8 * WS2;
                ah[ma][0] = WPh[r0 + kp];     ah[ma][1] = WPh[r1 + kp];
                ah[ma][2] = WPh[r0 + kp + 4]; ah[ma][3] = WPh[r1 + kp + 4];
                al[ma][0] = WPl[r0 + kp];     al[ma][1] = WPl[r1 + kp];
                al[ma][2] = WPl[r0 + kp + 4]; al[ma][3] = WPl[r1 + kp + 4];
            }
            #pragma unroll
            for (int na = 0; na < 4; na++){
                int col = ntile + na * 8 + grp;
                unsigned bh[2], bl[2];
                bh[0] = XPh[kp * XS2 + col]; bh[1] = XPh[(kp + 4) * XS2 + col];
                bl[0] = XPl[kp * XS2 + col]; bl[1] = XPl[(kp + 4) * XS2 + col];
                #pragma unroll
                for (int ma = 0; ma < 4; ma++){
                    mma_bf16(acc[ma][na], ah[ma], bh);
                    mma_bf16(acc[ma][na], ah[ma], bl);
                    mma_bf16(acc[ma][na], al[ma], bh);
                }
            }
        }
    }
    __syncthreads();

    #pragma unroll
    for (int ma = 0; ma < 4; ma++){
        float s0 = 0.f, s1 = 0.f;
        float m0 = __int_as_float(0xff800000), m1 = m0;
        #pragma unroll
        for (int na = 0; na < 4; na++){
            s0 += acc[ma][na][0] + acc[ma][na][1];
            s1 += acc[ma][na][2] + acc[ma][na][3];
            m0 = fmaxf(m0, fmaxf(acc[ma][na][0], acc[ma][na][1]));
            m1 = fmaxf(m1, fmaxf(acc[ma][na][2], acc[ma][na][3]));
        }
        #pragma unroll
        for (int st = 1; st <= 2; st <<= 1){
            s0 += __shfl_xor_sync(0xffffffffu, s0, st);
            s1 += __shfl_xor_sync(0xffffffffu, s1, st);
            m0 = fmaxf(m0, __shfl_xor_sync(0xffffffffu, m0, st));
            m1 = fmaxf(m1, __shfl_xor_sync(0xffffffffu, m1, st));
        }
        if (tig == 0){
            int co = mtile + ma * 16 + grp;
            atomicAdd(&ssum[co], s0);     atomicMaxF(&smax[co], m0);
            atomicAdd(&ssum[co + 8], s1); atomicMaxF(&smax[co + 8], m1);
        }
    }
    __syncthreads();
    if (tid < 128){
        atomicAdd(&g_avg[b * 128 + tid], ssum[tid]);
        atomicMaxF(&g_max[b * 128 + tid], smax[tid]);
    }
}

// ---------------- depthwise 3x3, multi-set ----------------
__global__ void dw3_kernel(
    const float* __restrict__ S0, float* __restrict__ D0, float* __restrict__ Q0, const float* __restrict__ Wd0,
    const float* __restrict__ S1, float* __restrict__ D1, float* __restrict__ Q1, const float* __restrict__ Wd1,
    const float* __restrict__ S2, float* __restrict__ D2, float* __restrict__ Q2, const float* __restrict__ Wd2)
{
    const float* X; float* Y; float* sq; const float* Wd;
    switch (blockIdx.y){
        case 0: X = S0; Y = D0; sq = Q0; Wd = Wd0; break;
        case 1: X = S1; Y = D1; sq = Q1; Wd = Wd1; break;
        default: X = S2; Y = D2; sq = Q2; Wd = Wd2; break;
    }
    int idx = blockIdx.x * 256 + threadIdx.x;
    int plane = idx / 2304;
    int r = idx - plane * 2304;
    int hp = r / 24, wb = r - hp * 24;
    int h = hp * 2, w = wb * 8;
    int c = plane & 127;
    const float* xp = X + plane * HW;
    const float* wdp = Wd + c * 9;
    float wd9[9];
    #pragma unroll
    for (int i = 0; i < 9; i++) wd9[i] = wdp[i];

    float ld[4][10];
    #pragma unroll
    for (int rr = 0; rr < 4; rr++){
        int hh = h - 1 + rr;
        if ((unsigned)hh < Hn){
            const float* rp_ = xp + hh * Wn + w;
            float4 a = *(const float4*)rp_;
            float4 bq = *(const float4*)(rp_ + 4);
            ld[rr][0] = (w > 0) ? rp_[-1] : 0.f;
            ld[rr][1] = a.x; ld[rr][2] = a.y; ld[rr][3] = a.z; ld[rr][4] = a.w;
            ld[rr][5] = bq.x; ld[rr][6] = bq.y; ld[rr][7] = bq.z; ld[rr][8] = bq.w;
            ld[rr][9] = (w + 8 < Wn) ? rp_[8] : 0.f;
        } else {
            #pragma unroll
            for (int j = 0; j < 10; j++) ld[rr][j] = 0.f;
        }
    }
    float o[2][8];
    #pragma unroll
    for (int orow = 0; orow < 2; orow++)
        #pragma unroll
        for (int j = 0; j < 8; j++) o[orow][j] = 0.f;
    #pragma unroll
    for (int orow = 0; orow < 2; orow++){
        #pragma unroll
        for (int t = 0; t < 3; t++){
            float k0 = wd9[t * 3 + 0], k1 = wd9[t * 3 + 1], k2 = wd9[t * 3 + 2];
            #pragma unroll
            for (int j = 0; j < 8; j++)
                o[orow][j] = fmaf(ld[orow + t][j], k0,
                             fmaf(ld[orow + t][j + 1], k1,
                             fmaf(ld[orow + t][j + 2], k2, o[orow][j])));
        }
    }
    #pragma unroll
    for (int orow = 0; orow < 2; orow++){
        float4 v0, v1;
        v0.x = o[orow][0]; v0.y = o[orow][1]; v0.z = o[orow][2]; v0.w = o[orow][3];
        v1.x = o[orow][4]; v1.y = o[orow][5]; v1.z = o[orow][6]; v1.w = o[orow][7];
        *(float4*)&Y[plane * HW + (h + orow) * Wn + w]     = v0;
        *(float4*)&Y[plane * HW + (h + orow) * Wn + w + 4] = v1;
    }
    if (sq){
        float s = 0.f;
        #pragma unroll
        for (int orow = 0; orow < 2; orow++)
            #pragma unroll
            for (int j = 0; j < 8; j++) s += o[orow][j] * o[orow][j];
        #pragma unroll
        for (int st = 16; st > 0; st >>= 1)
            s += __shfl_down_sync(0xffffffffu, s, st);
        if ((threadIdx.x & 31) == 0) atomicAdd(&sq[plane], s);
    }
}

// ---------------- gram: S += q k^T via bf16 3-term mma ----------------
__global__ void __launch_bounds__(256) gram_kernel(const float* __restrict__ Q,
                                                   const float* __restrict__ K){
    extern __shared__ unsigned smg[];
    unsigned* QAh = smg;
    unsigned* QAl = smg + GQPL;
    unsigned* KBh = smg + 2 * GQPL;
    unsigned* KBl = smg + 2 * GQPL + GKPL;
    int bn = blockIdx.y;
    int b = bn >> 1, n = bn & 1;
    const float* Qb = Q + b * CHW + n * HD * HW;
    const float* Kb = K + b * CHW + n * HD * HW;
    int tid = threadIdx.x, lane = tid & 31, wid = tid >> 5;
    int grp = lane >> 2, tig = lane & 3;
    int mtile = (wid >> 1) * 16, ntile = (wid & 1) * 32;

    float acc[4][4] = {};

    for (int ch = 0; ch < 4; ch++){
        int p0 = (blockIdx.x * 4 + ch) * 128;
        __syncthreads();
        // Q tile: 64 c x 128 p -> QA[c][kp], kp pairs along p
        #pragma unroll
        for (int it = 0; it < 8; it++){
            int c = wid + it * 8;
            float4 v = *(const float4*)(Qb + c * HW + p0 + lane * 4);
            unsigned h0, l0, h1, l1;
            packpair(v.x, v.y, h0, l0);
            packpair(v.z, v.w, h1, l1);
            int kp = lane * 2;
            QAh[c * GQS + kp]     = h0;  QAl[c * GQS + kp]     = l0;
            QAh[c * GQS + kp + 1] = h1;  QAl[c * GQS + kp + 1] = l1;
        }
        // K tile: 64 d x 128 p -> KB[kp][d] (transposed pack, phase-rotated writes)
        #pragma unroll
        for (int it = 0; it < 4; it++){
            int iter = wid + it * 8;          // 0..31
            int dblk = iter >> 2;             // 0..7
            int pblk = iter & 3;              // 0..3
            int d = dblk * 8 + (lane & 7);
            int pg = lane >> 3;               // 0..3
            int pl_ = pblk * 32 + pg * 8;     // chunk-local p
            float4 f0 = *(const float4*)(Kb + d * HW + p0 + pl_);
            float4 f1 = *(const float4*)(Kb + d * HW + p0 + pl_ + 4);
            unsigned wh[4], wl[4];
            packpair(f0.x, f0.y, wh[0], wl[0]);
            packpair(f0.z, f0.w, wh[1], wl[1]);
            packpair(f1.x, f1.y, wh[2], wl[2]);
            packpair(f1.z, f1.w, wh[3], wl[3]);
            int kp0 = pl_ >> 1;
            #pragma unroll
            for (int w = 0; w < 4; w++){
                int ws = (w + pg) & 3;
                KBh[(kp0 + ws) * GKS + d] = wh[ws];
                KBl[(kp0 + ws) * GKS + d] = wl[ws];
            }
        }
        __syncthreads();

        #pragma unroll
        for (int ks = 0; ks < 8; ks++){
            int kp = ks * 8 + tig;
            unsigned ah[4], al[4];
            int r0 = (mtile + grp) * GQS, r1 = r0 + 8 * GQS;
            ah[0] = QAh[r0 + kp]; ah[1] = QAh[r1 + kp];
            ah[2] = QAh[r0 + kp + 4]; ah[3] = QAh[r1 + kp + 4];
            al[0] = QAl[r0 + kp]; al[1] = QAl[r1 + kp];
            al[2] = QAl[r0 + kp + 4]; al[3] = QAl[r1 + kp + 4];
            #pragma unroll
            for (int na = 0; na < 4; na++){
                int col = ntile + na * 8 + grp;
                unsigned bh[2], bl[2];
                bh[0] = KBh[kp * GKS + col]; bh[1] = KBh[(kp + 4) * GKS + col];
                bl[0] = KBl[kp * GKS + col]; bl[1] = KBl[(kp + 4) * GKS + col];
                mma_bf16(acc[na], ah, bh);
                mma_bf16(acc[na], ah, bl);
                mma_bf16(acc[na], al, bh);
            }
        }
    }
    float* Sp = g_S + bn * 4096;
    #pragma unroll
    for (int na = 0; na < 4; na++){
        int c = mtile + grp;
        int d = ntile + na * 8 + tig * 2;
        atomicAdd(&Sp[c * 64 + d],           acc[na][0]);
        atomicAdd(&Sp[c * 64 + d + 1],       acc[na][1]);
        atomicAdd(&Sp[(c + 8) * 64 + d],     acc[na][2]);
        atomicAdd(&Sp[(c + 8) * 64 + d + 1], acc[na][3]);
    }
}

// ---------------- finalize attn + softmax + pack A for applyav ----------------
__global__ void attnfin_kernel(const float* __restrict__ scale, float* __restrict__ outAttn){
    int row = blockIdx.x;
    int d   = threadIdx.x;
    int b = row >> 7;
    int r = row & 127;
    int n = r >> 6;
    int c = r & 63;
    int bn = b * 2 + n;
    float nq = fmaxf(sqrtf(g_sq[b * 128 + r]), 1e-12f);
    float nk = fmaxf(sqrtf(g_sq[512 + b * 128 + (n << 6) + d]), 1e-12f);
    float val = g_S[row * 64 + d] / (nq * nk) * scale[n];
    outAttn[row * 64 + d] = val;
    __shared__ float sm[64];
    __shared__ float smp[64];
    sm[d] = val; __syncthreads();
    for (int st = 32; st > 0; st >>= 1){ if (d < st) sm[d] = fmaxf(sm[d], sm[d + st]); __syncthreads(); }
    float mx = sm[0]; __syncthreads();
    float e = expf(val - mx);
    sm[d] = e; __syncthreads();
    for (int st = 32; st > 0; st >>= 1){ if (d < st) sm[d] += sm[d + st]; __syncthreads(); }
    smp[d] = e / sm[0];
    __syncthreads();
    if (d < 32){
        unsigned wh, wl;
        packpair(smp[2 * d], smp[2 * d + 1], wh, wl);
        g_Apk[bn * 2 * AAPL + c * AAS + d]        = wh;
        g_Apk[bn * 2 * AAPL + AAPL + c * AAS + d] = wl;
    }
}

// ---------------- out = a @ v via bf16 mma, fused LN-stats ----------------
__global__ void __launch_bounds__(256) applyav_kernel(const float* __restrict__ V,
                                                      float* __restrict__ Out){
    extern __shared__ unsigned sma[];
    unsigned* APh = sma;
    unsigned* APl = sma + AAPL;
    unsigned* VPh = sma + 2 * AAPL;
    unsigned* VPl = sma + 2 * AAPL + AVPL;
    float* px_s  = (float*)(sma + 2 * AAPL + 2 * AVPL);
    float* px_s2 = px_s + 128;
    int bn = blockIdx.y;
    int b = bn >> 1, n = bn & 1;
    const float* Vb = V + b * CHW + n * HD * HW;
    int px0 = blockIdx.x * 128;
    int tid = threadIdx.x, lane = tid & 31, wid = tid >> 5;
    int grp = lane >> 2, tig = lane & 3;
    int mtile = (wid >> 1) * 16, ntile = (wid & 1) * 64;

    if (tid < 128){ px_s[tid] = 0.f; px_s2[tid] = 0.f; }

    {
        const unsigned* src = g_Apk + bn * 2 * AAPL;
        for (int i = tid; i < 2 * AAPL; i += 256) sma[i] = src[i];
    }
    #pragma unroll
    for (int i = 0; i < 4; i++){
        int idx = tid + i * 256;
        int r = idx >> 5, g = idx & 31;
        int px = g * 4;
        float4 x0 = *(const float4*)(Vb + (2 * r) * HW + px0 + px);
        float4 x1 = *(const float4*)(Vb + (2 * r + 1) * HW + px0 + px);
        uint4 vh, vl;
        packpair(x0.x, x1.x, vh.x, vl.x);
        packpair(x0.y, x1.y, vh.y, vl.y);
        packpair(x0.z, x1.z, vh.z, vl.z);
        packpair(x0.w, x1.w, vh.w, vl.w);
        *(uint4*)&VPh[r * AVS + px] = vh;
        *(uint4*)&VPl[r * AVS + px] = vl;
    }
    __syncthreads();

    float acc[8][4] = {};
    #pragma unroll
    for (int ks = 0; ks < 4; ks++){
        int kp = ks * 8 + tig;
        unsigned ah[4], al[4];
        int r0 = (mtile + grp) * AAS, r1 = r0 + 8 * AAS;
        ah[0] = APh[r0 + kp]; ah[1] = APh[r1 + kp];
        ah[2] = APh[r0 + kp + 4]; ah[3] = APh[r1 + kp + 4];
        al[0] = APl[r0 + kp]; al[1] = APl[r1 + kp];
        al[2] = APl[r0 + kp + 4]; al[3] = APl[r1 + kp + 4];
        #pragma unroll
        for (int na = 0; na < 8; na++){
            int col = ntile + na * 8 + grp;
            unsigned bh[2], bl[2];
            bh[0] = VPh[kp * AVS + col]; bh[1] = VPh[(kp + 4) * AVS + col];
            bl[0] = VPl[kp * AVS + col]; bl[1] = VPl[(kp + 4) * AVS + col];
            mma_bf16(acc[na], ah, bh);
            mma_bf16(acc[na], ah, bl);
            mma_bf16(acc[na], al, bh);
        }
    }
    float* Ob = Out + b * CHW + n * HD * HW + px0;
    #pragma unroll
    for (int na = 0; na < 8; na++){
        int c = mtile + grp;
        int px = ntile + na * 8 + tig * 2;
        *(float2*)&Ob[c * HW + px]       = make_float2(acc[na][0], acc[na][1]);
        *(float2*)&Ob[(c + 8) * HW + px] = make_float2(acc[na][2], acc[na][3]);
        float s0 = acc[na][0] + acc[na][2], s1 = acc[na][1] + acc[na][3];
        float q0 = acc[na][0] * acc[na][0] + acc[na][2] * acc[na][2];
        float q1 = acc[na][1] * acc[na][1] + acc[na][3] * acc[na][3];
        #pragma unroll
        for (int st = 4; st < 32; st <<= 1){
            s0 += __shfl_xor_sync(0xffffffffu, s0, st);
            s1 += __shfl_xor_sync(0xffffffffu, s1, st);
            q0 += __shfl_xor_sync(0xffffffffu, q0, st);
            q1 += __shfl_xor_sync(0xffffffffu, q1, st);
        }
        if (grp == 0){
            atomicAdd(&px_s[px], s0);      atomicAdd(&px_s[px + 1], s1);
            atomicAdd(&px_s2[px], q0);     atomicAdd(&px_s2[px + 1], q1);
        }
    }
    __syncthreads();
    if (tid < 128){
        int gp = b * HW + px0 + tid;
        atomicAdd(&g_mu[gp], px_s[tid]);
        atomicAdd(&g_rs[gp], px_s2[tid]);
    }
}

// ---------------- channel gate MLP ----------------
__global__ void gate_kernel(const float* __restrict__ w1, const float* __restrict__ b1,
                            const float* __restrict__ w2, const float* __restrict__ b2,
                            float* __restrict__ out){
    int b = blockIdx.x;
    int c = threadIdx.x;
    __shared__ float avg[128], mx[128], ha[8], hm[8];
    avg[c] = g_avg[b * 128 + c] * (1.0f / HW);
    mx[c]  = g_max[b * 128 + c];
    __syncthreads();
    if (c < 8){
        float sa = b1[c], sm_ = b1[c];
        for (int j = 0; j < 128; j++){
            sa  += w1[c * 128 + j] * avg[j];
            sm_ += w1[c * 128 + j] * mx[j];
        }
        ha[c] = fmaxf(sa, 0.f);
        hm[c] = fmaxf(sm_, 0.f);
    }
    __syncthreads();
    float z = 2.0f * b2[c];
    for (int j = 0; j < 8; j++) z += (ha[j] + hm[j]) * w2[c * 8 + j];
    out[b * 128 + c] = 1.0f / (1.0f + expf(-z));
}

// ---------------- launch ----------------
extern "C" void kernel_launch(void* const* d_in, const int* in_sizes, int n_in,
                              void* d_out, int out_size){
    const float* x        = (const float*)d_in[0];
    const float* ln_in_w  = (const float*)d_in[1];
    const float* ln_in_b  = (const float*)d_in[2];
    const float* wq_pw    = (const float*)d_in[3];
    const float* wq_dw    = (const float*)d_in[4];
    const float* wk_pw    = (const float*)d_in[5];
    const float* wk_dw    = (const float*)d_in[6];
    const float* wv_pw    = (const float*)d_in[7];
    const float* wv_dw    = (const float*)d_in[8];
    const float* scale    = (const float*)d_in[9];
    const float* ln_out_w = (const float*)d_in[10];
    const float* ln_out_b = (const float*)d_in[11];
    const float* f1_pw    = (const float*)d_in[12];
    const float* f1_dw    = (const float*)d_in[13];
    const float* f2_pw    = (const float*)d_in[14];
    const float* f2_dw    = (const float*)d_in[15];
    const float* f_out    = (const float*)d_in[16];
    const float* gw1      = (const float*)d_in[17];
    const float* gb1      = (const float*)d_in[18];
    const float* gw2      = (const float*)d_in[19];
    const float* gb2      = (const float*)d_in[20];
    float* out = (float*)d_out;

    cudaFuncSetAttribute(pwmulti_kernel,  cudaFuncAttributeMaxDynamicSharedMemorySize, SMEM_PW);
    cudaFuncSetAttribute(foutpool_kernel, cudaFuncAttributeMaxDynamicSharedMemorySize, SMEM_FP);
    cudaFuncSetAttribute(gram_kernel,     cudaFuncAttributeMaxDynamicSharedMemorySize, SMEM_G);
    cudaFuncSetAttribute(applyav_kernel,  cudaFuncAttributeMaxDynamicSharedMemorySize, SMEM_AV);

    void *p;
    float *B0,*B1,*B2,*B3,*B4,*B5,*SQ;
    cudaGetSymbolAddress(&p, g_B0);  B0  = (float*)p;
    cudaGetSymbolAddress(&p, g_B1);  B1  = (float*)p;
    cudaGetSymbolAddress(&p, g_B2);  B2  = (float*)p;
    cudaGetSymbolAddress(&p, g_B3);  B3  = (float*)p;
    cudaGetSymbolAddress(&p, g_B4);  B4  = (float*)p;
    cudaGetSymbolAddress(&p, g_B5);  B5  = (float*)p;
    cudaGetSymbolAddress(&p, g_sq);  SQ  = (float*)p;

    dim3 gpx(288, Bn);

    // 1-indexed launch 5 = pwmulti#1 for ncu (-s 5 -c 1)
    init_kernel<<<128, 256>>>();
    packw_kernel<<<dim3(16, 7), 256>>>(wq_pw, wk_pw, wv_pw, f1_pw, f2_pw, f_out);
    lnstats_kernel<<<576, 256>>>(x);
    nop_kernel<<<1, 1>>>();

    pwmulti_kernel<<<gpx, 256, SMEM_PW>>>(x, ln_in_w, ln_in_b,
                                          0, 1, 2, B0, B1, B5, 3, 0, 0);
    dw3_kernel<<<dim3(4608, 3), 256>>>(B0, B2, SQ,       wq_dw,
                                       B1, B3, SQ + 512, wk_dw,
                                       B5, B4, nullptr,  wv_dw);
    gram_kernel<<<dim3(GSPLIT, 8), 256, SMEM_G>>>(B2, B3);
    zero_mu_kernel<<<576, 256>>>();
    attnfin_kernel<<<512, 64>>>(scale, out + 512);
    applyav_kernel<<<dim3(288, 8), 256, SMEM_AV>>>(B4, B0);

    pwmulti_kernel<<<gpx, 256, SMEM_PW>>>(B0, ln_out_w, ln_out_b,
                                          3, 4, 4, B1, B5, nullptr, 2, 1, 1);
    dw3_kernel<<<dim3(4608, 2), 256>>>(B1, B2, nullptr, f1_dw,
                                       B5, B3, nullptr, f2_dw,
                                       nullptr, nullptr, nullptr, nullptr);
    foutpool_kernel<<<gpx, 256, SMEM_FP>>>(B2, B3);
    gate_kernel<<<4, 128>>>(gw1, gb1, gw2, gb2, out);
}